// round 3
// baseline (speedup 1.0000x reference)
#include <cuda_runtime.h>
#include <cuda_bf16.h>
#include <cstdint>

// Problem constants
#define B_   2
#define T_   2048
#define C_   1024
#define H_   16
#define HD_  64
#define M_   (B_*T_)    // 4096
#define BH_  (B_*H_)    // 32
#define SM_SCALE 0.125f // 1/sqrt(64)

// ---------------------------------------------------------------------------
// Scratch (device globals: allocation-guard safe)
// ---------------------------------------------------------------------------
__device__ float g_q[(size_t)BH_*T_*HD_];
__device__ float g_k[(size_t)BH_*T_*HD_];
__device__ float g_v[(size_t)BH_*T_*HD_];
__device__ float g_y[(size_t)M_*C_];
__device__ __nv_bfloat16 g_ahi[(size_t)M_*C_];
__device__ __nv_bfloat16 g_alo[(size_t)M_*C_];
__device__ __nv_bfloat16 g_whi[(size_t)C_*C_];   // W^T, [N][K]
__device__ __nv_bfloat16 g_wlo[(size_t)C_*C_];

// ---------------------------------------------------------------------------
// Base-target PTX helpers (sm_80+ features only: mma.sync / ldmatrix / cp.async)
// ---------------------------------------------------------------------------
__device__ __forceinline__ uint32_t smem_u32(const void* p) {
    uint32_t a;
    asm("{ .reg .u64 t; cvta.to.shared.u64 t, %1; cvt.u32.u64 %0, t; }"
        : "=r"(a) : "l"(p));
    return a;
}

__device__ __forceinline__ void cp16(uint32_t dst, const void* src) {
    asm volatile("{ .reg .u64 g; cvta.to.global.u64 g, %1;"
                 "  cp.async.cg.shared.global [%0], [g], 16; }"
                 :: "r"(dst), "l"(src) : "memory");
}
#define CP_COMMIT() asm volatile("cp.async.commit_group;" ::: "memory")
#define CP_WAIT(N)  asm volatile("cp.async.wait_group %0;" :: "n"(N) : "memory")

__device__ __forceinline__ void ldsm_x4(uint32_t* r, uint32_t addr) {
    asm volatile("ldmatrix.sync.aligned.m8n8.x4.shared.b16 {%0,%1,%2,%3}, [%4];"
                 : "=r"(r[0]), "=r"(r[1]), "=r"(r[2]), "=r"(r[3]) : "r"(addr));
}

__device__ __forceinline__ void mma_bf16(float* c, const uint32_t* a, const uint32_t* b) {
    asm volatile(
        "mma.sync.aligned.m16n8k16.row.col.f32.bf16.bf16.f32 "
        "{%0,%1,%2,%3}, {%4,%5,%6,%7}, {%8,%9}, {%0,%1,%2,%3};"
        : "+f"(c[0]), "+f"(c[1]), "+f"(c[2]), "+f"(c[3])
        : "r"(a[0]), "r"(a[1]), "r"(a[2]), "r"(a[3]), "r"(b[0]), "r"(b[1]));
}

// ---------------------------------------------------------------------------
// Conversion kernels: fp32 -> (hi, lo) bf16 split
// ---------------------------------------------------------------------------
__device__ __forceinline__ void split1(float v, __nv_bfloat16& h, __nv_bfloat16& l) {
    h = __float2bfloat16(v);
    l = __float2bfloat16(v - __bfloat162float(h));
}

__global__ void split_kernel(const float* __restrict__ X,
                             __nv_bfloat16* __restrict__ Hi,
                             __nv_bfloat16* __restrict__ Lo)
{
    const int i = (blockIdx.x * blockDim.x + threadIdx.x) * 4;
    float4 v = *(const float4*)(X + i);
    __nv_bfloat16 h[4], l[4];
    split1(v.x, h[0], l[0]); split1(v.y, h[1], l[1]);
    split1(v.z, h[2], l[2]); split1(v.w, h[3], l[3]);
    *(uint2*)(Hi + i) = *(uint2*)h;
    *(uint2*)(Lo + i) = *(uint2*)l;
}

// W [K=1024][N=1024] fp32 -> W^T [N][K] bf16 hi/lo
__global__ void wsplit_kernel(const float* __restrict__ W,
                              __nv_bfloat16* __restrict__ Hi,
                              __nv_bfloat16* __restrict__ Lo)
{
    __shared__ float tile[32][33];
    const int n0 = blockIdx.x * 32, k0 = blockIdx.y * 32;
    const int tx = threadIdx.x, ty = threadIdx.y;   // 32 x 8
    #pragma unroll
    for (int r = 0; r < 32; r += 8)
        tile[ty + r][tx] = W[(size_t)(k0 + ty + r) * C_ + n0 + tx];
    __syncthreads();
    #pragma unroll
    for (int r = 0; r < 32; r += 8) {
        const int n = n0 + ty + r, k = k0 + tx;
        __nv_bfloat16 h, l;
        split1(tile[tx][ty + r], h, l);
        Hi[(size_t)n * C_ + k] = h;
        Lo[(size_t)n * C_ + k] = l;
    }
}

// ---------------------------------------------------------------------------
// bf16-split GEMM via mma.sync: Out[m,n] = A[m,:]·W[:,n] + bias[n]
// A hi/lo [M][1024] bf16 row-major, B = W^T hi/lo [N][1024] bf16 row-major.
// 128x128 CTA tile, 8 warps (2m x 4n), warp tile 64x32, BK=32, double buffer.
// smem pitch 40 bf16 (80B) -> ldmatrix conflict-free.
// ---------------------------------------------------------------------------
#define PA 40
#define HALF_OFF   10240u            // 128*40*2 bytes
#define BBASE_OFF  20480u
#define BUF_BYTES  40960u
#define GEMM_SMEM  (2 * BUF_BYTES)

__global__ __launch_bounds__(256, 2)
void gemm_tc(const __nv_bfloat16* __restrict__ Ahi, const __nv_bfloat16* __restrict__ Alo,
             const __nv_bfloat16* __restrict__ Bhi, const __nv_bfloat16* __restrict__ Blo,
             const float* __restrict__ bias, float* __restrict__ Out, int split)
{
    extern __shared__ char sm[];
    const uint32_t sbase = smem_u32(sm);
    const int tid  = threadIdx.x;
    const int lane = tid & 31;
    const int wid  = tid >> 5;
    const int wm   = wid >> 2;       // 0..1
    const int wn   = wid & 3;        // 0..3
    const int brow = blockIdx.y * 128;
    const int bcol = blockIdx.x * 128;

    // load-role indices: idx = tid + i*256 -> row = idx>>2 (0..127), seg = idx&3
    const int r0 = tid >> 2, s0 = tid & 3;
    const int r1 = (tid + 256) >> 2, s1 = s0;

    float acc[4][4][4];
    #pragma unroll
    for (int mt = 0; mt < 4; mt++)
        #pragma unroll
        for (int nt = 0; nt < 4; nt++)
            #pragma unroll
            for (int e = 0; e < 4; e++) acc[mt][nt][e] = 0.f;

    // ---- async chunk loader -------------------------------------------------
    auto load_chunk = [&](int kc, int buf) {
        const uint32_t d0 = sbase + buf * BUF_BYTES;
        const size_t ka = (size_t)kc * 32;
        {   // rows r0 and r1 for all four arrays
            uint32_t dA0 = d0 + r0 * 80 + s0 * 16;
            uint32_t dA1 = d0 + r1 * 80 + s1 * 16;
            cp16(dA0,              Ahi + (size_t)(brow + r0) * C_ + ka + s0 * 8);
            cp16(dA1,              Ahi + (size_t)(brow + r1) * C_ + ka + s1 * 8);
            cp16(dA0 + HALF_OFF,   Alo + (size_t)(brow + r0) * C_ + ka + s0 * 8);
            cp16(dA1 + HALF_OFF,   Alo + (size_t)(brow + r1) * C_ + ka + s1 * 8);
            cp16(dA0 + BBASE_OFF,            Bhi + (size_t)(bcol + r0) * C_ + ka + s0 * 8);
            cp16(dA1 + BBASE_OFF,            Bhi + (size_t)(bcol + r1) * C_ + ka + s1 * 8);
            cp16(dA0 + BBASE_OFF + HALF_OFF, Blo + (size_t)(bcol + r0) * C_ + ka + s0 * 8);
            cp16(dA1 + BBASE_OFF + HALF_OFF, Blo + (size_t)(bcol + r1) * C_ + ka + s1 * 8);
        }
        CP_COMMIT();
    };

    load_chunk(0, 0);

    for (int kc = 0; kc < 32; kc++) {
        const int cur = kc & 1;
        if (kc + 1 < 32) { load_chunk(kc + 1, cur ^ 1); CP_WAIT(1); }
        else             { CP_WAIT(0); }
        __syncthreads();

        const uint32_t aB = sbase + cur * BUF_BYTES;
        const uint32_t bB = aB + BBASE_OFF;

        #pragma unroll
        for (int s = 0; s < 2; s++) {
            // B fragments: 4 n-tiles (warp cols 32), two x4 loads per half
            uint32_t bh[8], bl[8];
            #pragma unroll
            for (int p = 0; p < 2; p++) {
                const int nrow = wn * 32 + p * 16 + ((lane >> 4) & 1) * 8 + (lane & 7);
                const int col  = s * 16 + ((lane >> 3) & 1) * 8;
                const uint32_t bd = bB + (nrow * PA + col) * 2;
                ldsm_x4(&bh[p * 4], bd);
                ldsm_x4(&bl[p * 4], bd + HALF_OFF);
            }
            #pragma unroll
            for (int mt = 0; mt < 4; mt++) {
                const int arow = wm * 64 + mt * 16 + (lane & 15);
                const int acol = s * 16 + ((lane >> 4) << 3);
                const uint32_t ad = aB + (arow * PA + acol) * 2;
                uint32_t af[4];
                ldsm_x4(af, ad);                    // A hi
                #pragma unroll
                for (int nt = 0; nt < 4; nt++) {
                    mma_bf16(acc[mt][nt], af, &bh[nt * 2]);   // hi*hi
                    mma_bf16(acc[mt][nt], af, &bl[nt * 2]);   // hi*lo
                }
                ldsm_x4(af, ad + HALF_OFF);         // A lo
                #pragma unroll
                for (int nt = 0; nt < 4; nt++)
                    mma_bf16(acc[mt][nt], af, &bh[nt * 2]);   // lo*hi
            }
        }
        __syncthreads();
    }

    // ---- epilogue -----------------------------------------------------------
    const int g  = lane >> 2;
    const int tg = lane & 3;
    #pragma unroll
    for (int nt = 0; nt < 4; nt++) {
        const int n = bcol + wn * 32 + nt * 8 + tg * 2;
        const float bx = bias[n], by = bias[n + 1];
        #pragma unroll
        for (int mt = 0; mt < 4; mt++) {
            const int mr0 = brow + wm * 64 + mt * 16 + g;
            const int mr1 = mr0 + 8;
            float2 v0 = make_float2(acc[mt][nt][0] + bx, acc[mt][nt][1] + by);
            float2 v1 = make_float2(acc[mt][nt][2] + bx, acc[mt][nt][3] + by);
            if (!split) {
                *(float2*)(Out + (size_t)mr0 * C_ + n) = v0;
                *(float2*)(Out + (size_t)mr1 * C_ + n) = v1;
            } else {
                const int h = n >> 6, hd = n & 63;
                const int bb0 = mr0 >> 11, t0 = mr0 & 2047;
                const int bb1 = mr1 >> 11, t1 = mr1 & 2047;
                *(float2*)(Out + (((size_t)(bb0 * H_ + h) * T_) + t0) * HD_ + hd) = v0;
                *(float2*)(Out + (((size_t)(bb1 * H_ + h) * T_) + t1) * HD_ + hd) = v1;
            }
        }
    }
}

// ---------------------------------------------------------------------------
// Flash attention, fp32 (unchanged)
// ---------------------------------------------------------------------------
#define LDP 68
#define ATTN_SMEM (4 * 64 * LDP * 4)

__device__ __forceinline__ void load_tile_T(const float* __restrict__ src,
                                            float* dst, int tid, float scale)
{
    const int r  = tid >> 2;
    const int d0 = (tid & 3) << 4;
    #pragma unroll
    for (int i = 0; i < 4; i++) {
        float4 v = *(const float4*)(src + (size_t)r * HD_ + d0 + i * 4);
        const int d = d0 + i * 4;
        dst[(d + 0) * LDP + r] = v.x * scale;
        dst[(d + 1) * LDP + r] = v.y * scale;
        dst[(d + 2) * LDP + r] = v.z * scale;
        dst[(d + 3) * LDP + r] = v.w * scale;
    }
}

__device__ __forceinline__ void load_tile(const float* __restrict__ src,
                                          float* dst, int tid)
{
    const int r  = tid >> 2;
    const int d0 = (tid & 3) << 4;
    #pragma unroll
    for (int i = 0; i < 4; i++)
        *(float4*)(dst + (size_t)r * LDP + d0 + i * 4) =
            *(const float4*)(src + (size_t)r * HD_ + d0 + i * 4);
}

__global__ __launch_bounds__(256)
void attn_kernel(const float* __restrict__ Qg, const float* __restrict__ Kg,
                 const float* __restrict__ Vg, float* __restrict__ Yg)
{
    extern __shared__ float smem[];
    float* QsT = smem;
    float* KsT = QsT + 64 * LDP;
    float* Vs  = KsT + 64 * LDP;
    float* Ps  = Vs  + 64 * LDP;

    const int tid = threadIdx.x;
    const int qt  = blockIdx.x;
    const int bh  = blockIdx.y;
    const int ty4 = (tid >> 4) << 2;
    const int tx4 = (tid & 15) << 2;

    const float* Qb = Qg + (size_t)bh * T_ * HD_;
    const float* Kb = Kg + (size_t)bh * T_ * HD_;
    const float* Vb = Vg + (size_t)bh * T_ * HD_;

    load_tile_T(Qb + (size_t)qt * 64 * HD_, QsT, tid, SM_SCALE);

    float m_i[4], l_i[4], o[4][4];
    #pragma unroll
    for (int i = 0; i < 4; i++) {
        m_i[i] = -1e30f; l_i[i] = 0.f;
        #pragma unroll
        for (int j = 0; j < 4; j++) o[i][j] = 0.f;
    }

    for (int kt = 0; kt <= qt; kt++) {
        __syncthreads();
        load_tile_T(Kb + (size_t)kt * 64 * HD_, KsT, tid, 1.0f);
        load_tile  (Vb + (size_t)kt * 64 * HD_, Vs, tid);
        __syncthreads();

        float s[4][4];
        #pragma unroll
        for (int i = 0; i < 4; i++)
            #pragma unroll
            for (int j = 0; j < 4; j++) s[i][j] = 0.f;

        #pragma unroll 8
        for (int d = 0; d < 64; d++) {
            float a[4], b[4];
            *(float4*)a = *(const float4*)&QsT[d * LDP + ty4];
            *(float4*)b = *(const float4*)&KsT[d * LDP + tx4];
            #pragma unroll
            for (int i = 0; i < 4; i++)
                #pragma unroll
                for (int j = 0; j < 4; j++)
                    s[i][j] = fmaf(a[i], b[j], s[i][j]);
        }

        if (kt == qt) {
            #pragma unroll
            for (int i = 0; i < 4; i++)
                #pragma unroll
                for (int j = 0; j < 4; j++)
                    if (tx4 + j > ty4 + i) s[i][j] = -1e30f;
        }

        #pragma unroll
        for (int i = 0; i < 4; i++) {
            float mx = fmaxf(fmaxf(s[i][0], s[i][1]), fmaxf(s[i][2], s[i][3]));
            #pragma unroll
            for (int off = 8; off; off >>= 1)
                mx = fmaxf(mx, __shfl_xor_sync(0xffffffffu, mx, off));
            const float mn   = fmaxf(m_i[i], mx);
            const float corr = __expf(m_i[i] - mn);
            m_i[i] = mn;
            float ps = 0.f;
            #pragma unroll
            for (int j = 0; j < 4; j++) {
                s[i][j] = __expf(s[i][j] - mn);
                ps += s[i][j];
            }
            #pragma unroll
            for (int off = 8; off; off >>= 1)
                ps += __shfl_xor_sync(0xffffffffu, ps, off);
            l_i[i] = l_i[i] * corr + ps;
            #pragma unroll
            for (int j = 0; j < 4; j++) o[i][j] *= corr;
        }

        #pragma unroll
        for (int j = 0; j < 4; j++) {
            float4 pv = make_float4(s[0][j], s[1][j], s[2][j], s[3][j]);
            *(float4*)&Ps[(tx4 + j) * LDP + ty4] = pv;
        }
        __syncthreads();

        #pragma unroll 8
        for (int k = 0; k < 64; k++) {
            float a[4], b[4];
            *(float4*)a = *(const float4*)&Ps[k * LDP + ty4];
            *(float4*)b = *(const float4*)&Vs[k * LDP + tx4];
            #pragma unroll
            for (int i = 0; i < 4; i++)
                #pragma unroll
                for (int j = 0; j < 4; j++)
                    o[i][j] = fmaf(a[i], b[j], o[i][j]);
        }
    }

    const int bb = bh >> 4;
    const int h  = bh & 15;
    #pragma unroll
    for (int i = 0; i < 4; i++) {
        const float inv = 1.0f / l_i[i];
        const int t = qt * 64 + ty4 + i;
        float4 yv = make_float4(o[i][0]*inv, o[i][1]*inv, o[i][2]*inv, o[i][3]*inv);
        *(float4*)(Yg + ((size_t)(bb * T_ + t)) * C_ + h * HD_ + tx4) = yv;
    }
}

// ---------------------------------------------------------------------------
extern "C" void kernel_launch(void* const* d_in, const int* in_sizes, int n_in,
                              void* d_out, int out_size)
{
    const float* query = (const float*)d_in[0];
    const float* key   = (const float*)d_in[1];
    const float* value = (const float*)d_in[2];
    // d_in[3] = att_mask (causal tril; provably unused)
    const float* Wq = (const float*)d_in[4];
    const float* bq = (const float*)d_in[5];
    const float* Wk = (const float*)d_in[6];
    const float* bk = (const float*)d_in[7];
    const float* Wv = (const float*)d_in[8];
    const float* bv = (const float*)d_in[9];
    const float* Wp = (const float*)d_in[10];
    const float* bp = (const float*)d_in[11];
    float* out = (float*)d_out;

    float *gq, *gk, *gv, *gy;
    __nv_bfloat16 *ahi, *alo, *whi, *wlo;
    cudaGetSymbolAddress((void**)&gq, g_q);
    cudaGetSymbolAddress((void**)&gk, g_k);
    cudaGetSymbolAddress((void**)&gv, g_v);
    cudaGetSymbolAddress((void**)&gy, g_y);
    cudaGetSymbolAddress((void**)&ahi, g_ahi);
    cudaGetSymbolAddress((void**)&alo, g_alo);
    cudaGetSymbolAddress((void**)&whi, g_whi);
    cudaGetSymbolAddress((void**)&wlo, g_wlo);

    cudaFuncSetAttribute(attn_kernel,
                         cudaFuncAttributeMaxDynamicSharedMemorySize, ATTN_SMEM);
    cudaFuncSetAttribute(gemm_tc,
                         cudaFuncAttributeMaxDynamicSharedMemorySize, GEMM_SMEM);

    const int SPLIT_BLK = 256;
    const int nsplit = (M_ * C_) / (SPLIT_BLK * 4);
    dim3 wgrid(C_ / 32, C_ / 32), wblk(32, 8);
    dim3 ggrid(C_ / 128, M_ / 128);   // (8, 32)

    // Q projection
    split_kernel<<<nsplit, SPLIT_BLK>>>(query, ahi, alo);
    wsplit_kernel<<<wgrid, wblk>>>(Wq, whi, wlo);
    gemm_tc<<<ggrid, 256, GEMM_SMEM>>>(ahi, alo, whi, wlo, bq, gq, 1);
    // K projection
    split_kernel<<<nsplit, SPLIT_BLK>>>(key, ahi, alo);
    wsplit_kernel<<<wgrid, wblk>>>(Wk, whi, wlo);
    gemm_tc<<<ggrid, 256, GEMM_SMEM>>>(ahi, alo, whi, wlo, bk, gk, 1);
    // V projection
    split_kernel<<<nsplit, SPLIT_BLK>>>(value, ahi, alo);
    wsplit_kernel<<<wgrid, wblk>>>(Wv, whi, wlo);
    gemm_tc<<<ggrid, 256, GEMM_SMEM>>>(ahi, alo, whi, wlo, bv, gv, 1);

    attn_kernel<<<dim3(T_ / 64, BH_), 256, ATTN_SMEM>>>(gq, gk, gv, gy);

    // output projection
    split_kernel<<<nsplit, SPLIT_BLK>>>(gy, ahi, alo);
    wsplit_kernel<<<wgrid, wblk>>>(Wp, whi, wlo);
    gemm_tc<<<ggrid, 256, GEMM_SMEM>>>(ahi, alo, whi, wlo, bp, out, 0);
}

// round 4
// speedup vs baseline: 1.5908x; 1.5908x over previous
#include <cuda_runtime.h>
#include <cuda_bf16.h>
#include <cstdint>

// Problem constants
#define B_   2
#define T_   2048
#define C_   1024
#define H_   16
#define HD_  64
#define M_   (B_*T_)    // 4096
#define BH_  (B_*H_)    // 32
#define SM_SCALE 0.125f // 1/sqrt(64)

// ---------------------------------------------------------------------------
// Scratch (device globals: allocation-guard safe)
// ---------------------------------------------------------------------------
__device__ float g_q[(size_t)BH_*T_*HD_];
__device__ float g_k[(size_t)BH_*T_*HD_];
__device__ float g_v[(size_t)BH_*T_*HD_];
__device__ float g_y[(size_t)M_*C_];
__device__ __nv_bfloat16 g_ahi[(size_t)M_*C_];
__device__ __nv_bfloat16 g_alo[(size_t)M_*C_];
__device__ __nv_bfloat16 g_whi[(size_t)C_*C_];   // W^T, [N][K]
__device__ __nv_bfloat16 g_wlo[(size_t)C_*C_];

// ---------------------------------------------------------------------------
// Base-target PTX helpers (sm_80+ features only: mma.sync / ldmatrix / cp.async)
// ---------------------------------------------------------------------------
__device__ __forceinline__ uint32_t smem_u32(const void* p) {
    uint32_t a;
    asm("{ .reg .u64 t; cvta.to.shared.u64 t, %1; cvt.u32.u64 %0, t; }"
        : "=r"(a) : "l"(p));
    return a;
}

__device__ __forceinline__ void cp16(uint32_t dst, const void* src) {
    asm volatile("{ .reg .u64 g; cvta.to.global.u64 g, %1;"
                 "  cp.async.cg.shared.global [%0], [g], 16; }"
                 :: "r"(dst), "l"(src) : "memory");
}
#define CP_COMMIT() asm volatile("cp.async.commit_group;" ::: "memory")
#define CP_WAIT(N)  asm volatile("cp.async.wait_group %0;" :: "n"(N) : "memory")

__device__ __forceinline__ void ldsm_x4(uint32_t* r, uint32_t addr) {
    asm volatile("ldmatrix.sync.aligned.m8n8.x4.shared.b16 {%0,%1,%2,%3}, [%4];"
                 : "=r"(r[0]), "=r"(r[1]), "=r"(r[2]), "=r"(r[3]) : "r"(addr));
}

__device__ __forceinline__ void mma_bf16(float* c, const uint32_t* a, const uint32_t* b) {
    asm volatile(
        "mma.sync.aligned.m16n8k16.row.col.f32.bf16.bf16.f32 "
        "{%0,%1,%2,%3}, {%4,%5,%6,%7}, {%8,%9}, {%0,%1,%2,%3};"
        : "+f"(c[0]), "+f"(c[1]), "+f"(c[2]), "+f"(c[3])
        : "r"(a[0]), "r"(a[1]), "r"(a[2]), "r"(a[3]), "r"(b[0]), "r"(b[1]));
}

// ---------------------------------------------------------------------------
// Conversion kernels: fp32 -> (hi, lo) bf16 split
// ---------------------------------------------------------------------------
__device__ __forceinline__ void split1(float v, __nv_bfloat16& h, __nv_bfloat16& l) {
    h = __float2bfloat16(v);
    l = __float2bfloat16(v - __bfloat162float(h));
}

__global__ void split_kernel(const float* __restrict__ X,
                             __nv_bfloat16* __restrict__ Hi,
                             __nv_bfloat16* __restrict__ Lo)
{
    const int i = (blockIdx.x * blockDim.x + threadIdx.x) * 4;
    float4 v = *(const float4*)(X + i);
    __nv_bfloat16 h[4], l[4];
    split1(v.x, h[0], l[0]); split1(v.y, h[1], l[1]);
    split1(v.z, h[2], l[2]); split1(v.w, h[3], l[3]);
    *(uint2*)(Hi + i) = *(uint2*)h;
    *(uint2*)(Lo + i) = *(uint2*)l;
}

// W [K=1024][N=1024] fp32 -> W^T [N][K] bf16 hi/lo
__global__ void wsplit_kernel(const float* __restrict__ W,
                              __nv_bfloat16* __restrict__ Hi,
                              __nv_bfloat16* __restrict__ Lo)
{
    __shared__ float tile[32][33];
    const int n0 = blockIdx.x * 32, k0 = blockIdx.y * 32;
    const int tx = threadIdx.x, ty = threadIdx.y;   // 32 x 8
    #pragma unroll
    for (int r = 0; r < 32; r += 8)
        tile[ty + r][tx] = W[(size_t)(k0 + ty + r) * C_ + n0 + tx];
    __syncthreads();
    #pragma unroll
    for (int r = 0; r < 32; r += 8) {
        const int n = n0 + ty + r, k = k0 + tx;
        __nv_bfloat16 h, l;
        split1(tile[tx][ty + r], h, l);
        Hi[(size_t)n * C_ + k] = h;
        Lo[(size_t)n * C_ + k] = l;
    }
}

// ---------------------------------------------------------------------------
// bf16-split GEMM via mma.sync: Out[m,n] = A[m,:]·W[:,n] + bias[n]
// A hi/lo [M][1024] bf16 row-major, B = W^T hi/lo [N][1024] bf16 row-major.
// 128x128 CTA tile, 8 warps (2m x 4n), warp tile 64x32, BK=32, double buffer.
// smem pitch 40 bf16 (80B) -> ldmatrix conflict-free.
// ---------------------------------------------------------------------------
#define PA 40
#define HALF_OFF   10240u            // 128*40*2 bytes
#define BBASE_OFF  20480u
#define BUF_BYTES  40960u
#define GEMM_SMEM  (2 * BUF_BYTES)

__global__ __launch_bounds__(256, 2)
void gemm_tc(const __nv_bfloat16* __restrict__ Ahi, const __nv_bfloat16* __restrict__ Alo,
             const __nv_bfloat16* __restrict__ Bhi, const __nv_bfloat16* __restrict__ Blo,
             const float* __restrict__ bias, float* __restrict__ Out, int split)
{
    extern __shared__ char sm[];
    const uint32_t sbase = smem_u32(sm);
    const int tid  = threadIdx.x;
    const int lane = tid & 31;
    const int wid  = tid >> 5;
    const int wm   = wid >> 2;       // 0..1
    const int wn   = wid & 3;        // 0..3
    const int brow = blockIdx.y * 128;
    const int bcol = blockIdx.x * 128;

    // load-role indices: idx = tid + i*256 -> row = idx>>2 (0..127), seg = idx&3
    const int r0 = tid >> 2, s0 = tid & 3;
    const int r1 = (tid + 256) >> 2, s1 = s0;

    float acc[4][4][4];
    #pragma unroll
    for (int mt = 0; mt < 4; mt++)
        #pragma unroll
        for (int nt = 0; nt < 4; nt++)
            #pragma unroll
            for (int e = 0; e < 4; e++) acc[mt][nt][e] = 0.f;

    // ---- async chunk loader -------------------------------------------------
    auto load_chunk = [&](int kc, int buf) {
        const uint32_t d0 = sbase + buf * BUF_BYTES;
        const size_t ka = (size_t)kc * 32;
        {   // rows r0 and r1 for all four arrays
            uint32_t dA0 = d0 + r0 * 80 + s0 * 16;
            uint32_t dA1 = d0 + r1 * 80 + s1 * 16;
            cp16(dA0,              Ahi + (size_t)(brow + r0) * C_ + ka + s0 * 8);
            cp16(dA1,              Ahi + (size_t)(brow + r1) * C_ + ka + s1 * 8);
            cp16(dA0 + HALF_OFF,   Alo + (size_t)(brow + r0) * C_ + ka + s0 * 8);
            cp16(dA1 + HALF_OFF,   Alo + (size_t)(brow + r1) * C_ + ka + s1 * 8);
            cp16(dA0 + BBASE_OFF,            Bhi + (size_t)(bcol + r0) * C_ + ka + s0 * 8);
            cp16(dA1 + BBASE_OFF,            Bhi + (size_t)(bcol + r1) * C_ + ka + s1 * 8);
            cp16(dA0 + BBASE_OFF + HALF_OFF, Blo + (size_t)(bcol + r0) * C_ + ka + s0 * 8);
            cp16(dA1 + BBASE_OFF + HALF_OFF, Blo + (size_t)(bcol + r1) * C_ + ka + s1 * 8);
        }
        CP_COMMIT();
    };

    load_chunk(0, 0);

    for (int kc = 0; kc < 32; kc++) {
        const int cur = kc & 1;
        if (kc + 1 < 32) { load_chunk(kc + 1, cur ^ 1); CP_WAIT(1); }
        else             { CP_WAIT(0); }
        __syncthreads();

        const uint32_t aB = sbase + cur * BUF_BYTES;
        const uint32_t bB = aB + BBASE_OFF;

        #pragma unroll
        for (int s = 0; s < 2; s++) {
            // B fragments: 4 n-tiles (warp cols 32), two x4 loads per half
            uint32_t bh[8], bl[8];
            #pragma unroll
            for (int p = 0; p < 2; p++) {
                const int nrow = wn * 32 + p * 16 + ((lane >> 4) & 1) * 8 + (lane & 7);
                const int col  = s * 16 + ((lane >> 3) & 1) * 8;
                const uint32_t bd = bB + (nrow * PA + col) * 2;
                ldsm_x4(&bh[p * 4], bd);
                ldsm_x4(&bl[p * 4], bd + HALF_OFF);
            }
            #pragma unroll
            for (int mt = 0; mt < 4; mt++) {
                const int arow = wm * 64 + mt * 16 + (lane & 15);
                const int acol = s * 16 + ((lane >> 4) << 3);
                const uint32_t ad = aB + (arow * PA + acol) * 2;
                uint32_t af[4];
                ldsm_x4(af, ad);                    // A hi
                #pragma unroll
                for (int nt = 0; nt < 4; nt++) {
                    mma_bf16(acc[mt][nt], af, &bh[nt * 2]);   // hi*hi
                    mma_bf16(acc[mt][nt], af, &bl[nt * 2]);   // hi*lo
                }
                ldsm_x4(af, ad + HALF_OFF);         // A lo
                #pragma unroll
                for (int nt = 0; nt < 4; nt++)
                    mma_bf16(acc[mt][nt], af, &bh[nt * 2]);   // lo*hi
            }
        }
        __syncthreads();
    }

    // ---- epilogue -----------------------------------------------------------
    const int g  = lane >> 2;
    const int tg = lane & 3;
    #pragma unroll
    for (int nt = 0; nt < 4; nt++) {
        const int n = bcol + wn * 32 + nt * 8 + tg * 2;
        const float bx = bias[n], by = bias[n + 1];
        #pragma unroll
        for (int mt = 0; mt < 4; mt++) {
            const int mr0 = brow + wm * 64 + mt * 16 + g;
            const int mr1 = mr0 + 8;
            float2 v0 = make_float2(acc[mt][nt][0] + bx, acc[mt][nt][1] + by);
            float2 v1 = make_float2(acc[mt][nt][2] + bx, acc[mt][nt][3] + by);
            if (!split) {
                *(float2*)(Out + (size_t)mr0 * C_ + n) = v0;
                *(float2*)(Out + (size_t)mr1 * C_ + n) = v1;
            } else {
                const int h = n >> 6, hd = n & 63;
                const int bb0 = mr0 >> 11, t0 = mr0 & 2047;
                const int bb1 = mr1 >> 11, t1 = mr1 & 2047;
                *(float2*)(Out + (((size_t)(bb0 * H_ + h) * T_) + t0) * HD_ + hd) = v0;
                *(float2*)(Out + (((size_t)(bb1 * H_ + h) * T_) + t1) * HD_ + hd) = v1;
            }
        }
    }
}

// ---------------------------------------------------------------------------
// Flash attention, fp32 (unchanged)
// ---------------------------------------------------------------------------
#define LDP 68
#define ATTN_SMEM (4 * 64 * LDP * 4)

__device__ __forceinline__ void load_tile_T(const float* __restrict__ src,
                                            float* dst, int tid, float scale)
{
    const int r  = tid >> 2;
    const int d0 = (tid & 3) << 4;
    #pragma unroll
    for (int i = 0; i < 4; i++) {
        float4 v = *(const float4*)(src + (size_t)r * HD_ + d0 + i * 4);
        const int d = d0 + i * 4;
        dst[(d + 0) * LDP + r] = v.x * scale;
        dst[(d + 1) * LDP + r] = v.y * scale;
        dst[(d + 2) * LDP + r] = v.z * scale;
        dst[(d + 3) * LDP + r] = v.w * scale;
    }
}

__device__ __forceinline__ void load_tile(const float* __restrict__ src,
                                          float* dst, int tid)
{
    const int r  = tid >> 2;
    const int d0 = (tid & 3) << 4;
    #pragma unroll
    for (int i = 0; i < 4; i++)
        *(float4*)(dst + (size_t)r * LDP + d0 + i * 4) =
            *(const float4*)(src + (size_t)r * HD_ + d0 + i * 4);
}

__global__ __launch_bounds__(256)
void attn_kernel(const float* __restrict__ Qg, const float* __restrict__ Kg,
                 const float* __restrict__ Vg, float* __restrict__ Yg)
{
    extern __shared__ float smem[];
    float* QsT = smem;
    float* KsT = QsT + 64 * LDP;
    float* Vs  = KsT + 64 * LDP;
    float* Ps  = Vs  + 64 * LDP;

    const int tid = threadIdx.x;
    const int qt  = blockIdx.x;
    const int bh  = blockIdx.y;
    const int ty4 = (tid >> 4) << 2;
    const int tx4 = (tid & 15) << 2;

    const float* Qb = Qg + (size_t)bh * T_ * HD_;
    const float* Kb = Kg + (size_t)bh * T_ * HD_;
    const float* Vb = Vg + (size_t)bh * T_ * HD_;

    load_tile_T(Qb + (size_t)qt * 64 * HD_, QsT, tid, SM_SCALE);

    float m_i[4], l_i[4], o[4][4];
    #pragma unroll
    for (int i = 0; i < 4; i++) {
        m_i[i] = -1e30f; l_i[i] = 0.f;
        #pragma unroll
        for (int j = 0; j < 4; j++) o[i][j] = 0.f;
    }

    for (int kt = 0; kt <= qt; kt++) {
        __syncthreads();
        load_tile_T(Kb + (size_t)kt * 64 * HD_, KsT, tid, 1.0f);
        load_tile  (Vb + (size_t)kt * 64 * HD_, Vs, tid);
        __syncthreads();

        float s[4][4];
        #pragma unroll
        for (int i = 0; i < 4; i++)
            #pragma unroll
            for (int j = 0; j < 4; j++) s[i][j] = 0.f;

        #pragma unroll 8
        for (int d = 0; d < 64; d++) {
            float a[4], b[4];
            *(float4*)a = *(const float4*)&QsT[d * LDP + ty4];
            *(float4*)b = *(const float4*)&KsT[d * LDP + tx4];
            #pragma unroll
            for (int i = 0; i < 4; i++)
                #pragma unroll
                for (int j = 0; j < 4; j++)
                    s[i][j] = fmaf(a[i], b[j], s[i][j]);
        }

        if (kt == qt) {
            #pragma unroll
            for (int i = 0; i < 4; i++)
                #pragma unroll
                for (int j = 0; j < 4; j++)
                    if (tx4 + j > ty4 + i) s[i][j] = -1e30f;
        }

        #pragma unroll
        for (int i = 0; i < 4; i++) {
            float mx = fmaxf(fmaxf(s[i][0], s[i][1]), fmaxf(s[i][2], s[i][3]));
            #pragma unroll
            for (int off = 8; off; off >>= 1)
                mx = fmaxf(mx, __shfl_xor_sync(0xffffffffu, mx, off));
            const float mn   = fmaxf(m_i[i], mx);
            const float corr = __expf(m_i[i] - mn);
            m_i[i] = mn;
            float ps = 0.f;
            #pragma unroll
            for (int j = 0; j < 4; j++) {
                s[i][j] = __expf(s[i][j] - mn);
                ps += s[i][j];
            }
            #pragma unroll
            for (int off = 8; off; off >>= 1)
                ps += __shfl_xor_sync(0xffffffffu, ps, off);
            l_i[i] = l_i[i] * corr + ps;
            #pragma unroll
            for (int j = 0; j < 4; j++) o[i][j] *= corr;
        }

        #pragma unroll
        for (int j = 0; j < 4; j++) {
            float4 pv = make_float4(s[0][j], s[1][j], s[2][j], s[3][j]);
            *(float4*)&Ps[(tx4 + j) * LDP + ty4] = pv;
        }
        __syncthreads();

        #pragma unroll 8
        for (int k = 0; k < 64; k++) {
            float a[4], b[4];
            *(float4*)a = *(const float4*)&Ps[k * LDP + ty4];
            *(float4*)b = *(const float4*)&Vs[k * LDP + tx4];
            #pragma unroll
            for (int i = 0; i < 4; i++)
                #pragma unroll
                for (int j = 0; j < 4; j++)
                    o[i][j] = fmaf(a[i], b[j], o[i][j]);
        }
    }

    const int bb = bh >> 4;
    const int h  = bh & 15;
    #pragma unroll
    for (int i = 0; i < 4; i++) {
        const float inv = 1.0f / l_i[i];
        const int t = qt * 64 + ty4 + i;
        float4 yv = make_float4(o[i][0]*inv, o[i][1]*inv, o[i][2]*inv, o[i][3]*inv);
        *(float4*)(Yg + ((size_t)(bb * T_ + t)) * C_ + h * HD_ + tx4) = yv;
    }
}

// ---------------------------------------------------------------------------
extern "C" void kernel_launch(void* const* d_in, const int* in_sizes, int n_in,
                              void* d_out, int out_size)
{
    const float* query = (const float*)d_in[0];
    const float* key   = (const float*)d_in[1];
    const float* value = (const float*)d_in[2];
    // d_in[3] = att_mask (causal tril; provably unused)
    const float* Wq = (const float*)d_in[4];
    const float* bq = (const float*)d_in[5];
    const float* Wk = (const float*)d_in[6];
    const float* bk = (const float*)d_in[7];
    const float* Wv = (const float*)d_in[8];
    const float* bv = (const float*)d_in[9];
    const float* Wp = (const float*)d_in[10];
    const float* bp = (const float*)d_in[11];
    float* out = (float*)d_out;

    float *gq, *gk, *gv, *gy;
    __nv_bfloat16 *ahi, *alo, *whi, *wlo;
    cudaGetSymbolAddress((void**)&gq, g_q);
    cudaGetSymbolAddress((void**)&gk, g_k);
    cudaGetSymbolAddress((void**)&gv, g_v);
    cudaGetSymbolAddress((void**)&gy, g_y);
    cudaGetSymbolAddress((void**)&ahi, g_ahi);
    cudaGetSymbolAddress((void**)&alo, g_alo);
    cudaGetSymbolAddress((void**)&whi, g_whi);
    cudaGetSymbolAddress((void**)&wlo, g_wlo);

    cudaFuncSetAttribute(attn_kernel,
                         cudaFuncAttributeMaxDynamicSharedMemorySize, ATTN_SMEM);
    cudaFuncSetAttribute(gemm_tc,
                         cudaFuncAttributeMaxDynamicSharedMemorySize, GEMM_SMEM);

    const int SPLIT_BLK = 256;
    const int nsplit = (M_ * C_) / (SPLIT_BLK * 4);
    dim3 wgrid(C_ / 32, C_ / 32), wblk(32, 8);
    dim3 ggrid(C_ / 128, M_ / 128);   // (8, 32)

    // Q projection
    split_kernel<<<nsplit, SPLIT_BLK>>>(query, ahi, alo);
    wsplit_kernel<<<wgrid, wblk>>>(Wq, whi, wlo);
    gemm_tc<<<ggrid, 256, GEMM_SMEM>>>(ahi, alo, whi, wlo, bq, gq, 1);
    // K projection
    split_kernel<<<nsplit, SPLIT_BLK>>>(key, ahi, alo);
    wsplit_kernel<<<wgrid, wblk>>>(Wk, whi, wlo);
    gemm_tc<<<ggrid, 256, GEMM_SMEM>>>(ahi, alo, whi, wlo, bk, gk, 1);
    // V projection
    split_kernel<<<nsplit, SPLIT_BLK>>>(value, ahi, alo);
    wsplit_kernel<<<wgrid, wblk>>>(Wv, whi, wlo);
    gemm_tc<<<ggrid, 256, GEMM_SMEM>>>(ahi, alo, whi, wlo, bv, gv, 1);

    attn_kernel<<<dim3(T_ / 64, BH_), 256, ATTN_SMEM>>>(gq, gk, gv, gy);

    // output projection
    split_kernel<<<nsplit, SPLIT_BLK>>>(gy, ahi, alo);
    wsplit_kernel<<<wgrid, wblk>>>(Wp, whi, wlo);
    gemm_tc<<<ggrid, 256, GEMM_SMEM>>>(ahi, alo, whi, wlo, bp, out, 0);
}

// round 5
// speedup vs baseline: 2.9915x; 1.8805x over previous
#include <cuda_runtime.h>
#include <cuda_bf16.h>
#include <cstdint>

// Problem constants
#define B_   2
#define T_   2048
#define C_   1024
#define H_   16
#define HD_  64
#define M_   (B_*T_)    // 4096
#define BH_  (B_*H_)    // 32
#define SM_SCALE 0.125f // 1/sqrt(64)

// ---------------------------------------------------------------------------
// Scratch (device globals: allocation-guard safe)
// ---------------------------------------------------------------------------
__device__ float g_q[(size_t)BH_*T_*HD_];
__device__ float g_k[(size_t)BH_*T_*HD_];
__device__ float g_v[(size_t)BH_*T_*HD_];
__device__ float g_y[(size_t)M_*C_];
__device__ __nv_bfloat16 g_ahi[(size_t)M_*C_];
__device__ __nv_bfloat16 g_alo[(size_t)M_*C_];
__device__ __nv_bfloat16 g_whi[(size_t)C_*C_];   // W^T, [N][K]
__device__ __nv_bfloat16 g_wlo[(size_t)C_*C_];
// attention operand splits
__device__ __nv_bfloat16 g_qhi[(size_t)BH_*T_*HD_];
__device__ __nv_bfloat16 g_qlo[(size_t)BH_*T_*HD_];
__device__ __nv_bfloat16 g_khi[(size_t)BH_*T_*HD_];
__device__ __nv_bfloat16 g_klo[(size_t)BH_*T_*HD_];
__device__ __nv_bfloat16 g_vthi[(size_t)BH_*HD_*T_];  // transposed [bh][d][t]
__device__ __nv_bfloat16 g_vtlo[(size_t)BH_*HD_*T_];

// ---------------------------------------------------------------------------
// Base-target PTX helpers (sm_80+ features only)
// ---------------------------------------------------------------------------
__device__ __forceinline__ uint32_t smem_u32(const void* p) {
    uint32_t a;
    asm("{ .reg .u64 t; cvta.to.shared.u64 t, %1; cvt.u32.u64 %0, t; }"
        : "=r"(a) : "l"(p));
    return a;
}
__device__ __forceinline__ void cp16(uint32_t dst, const void* src) {
    asm volatile("{ .reg .u64 g; cvta.to.global.u64 g, %1;"
                 "  cp.async.cg.shared.global [%0], [g], 16; }"
                 :: "r"(dst), "l"(src) : "memory");
}
#define CP_COMMIT() asm volatile("cp.async.commit_group;" ::: "memory")
#define CP_WAIT(N)  asm volatile("cp.async.wait_group %0;" :: "n"(N) : "memory")

__device__ __forceinline__ void ldsm_x4(uint32_t* r, uint32_t addr) {
    asm volatile("ldmatrix.sync.aligned.m8n8.x4.shared.b16 {%0,%1,%2,%3}, [%4];"
                 : "=r"(r[0]), "=r"(r[1]), "=r"(r[2]), "=r"(r[3]) : "r"(addr));
}
__device__ __forceinline__ void mma_bf16(float* c, const uint32_t* a, const uint32_t* b) {
    asm volatile(
        "mma.sync.aligned.m16n8k16.row.col.f32.bf16.bf16.f32 "
        "{%0,%1,%2,%3}, {%4,%5,%6,%7}, {%8,%9}, {%0,%1,%2,%3};"
        : "+f"(c[0]), "+f"(c[1]), "+f"(c[2]), "+f"(c[3])
        : "r"(a[0]), "r"(a[1]), "r"(a[2]), "r"(a[3]), "r"(b[0]), "r"(b[1]));
}

// ---------------------------------------------------------------------------
// Conversion kernels
// ---------------------------------------------------------------------------
__device__ __forceinline__ void split1(float v, __nv_bfloat16& h, __nv_bfloat16& l) {
    h = __float2bfloat16(v);
    l = __float2bfloat16(v - __bfloat162float(h));
}

__global__ void split_kernel(const float* __restrict__ X,
                             __nv_bfloat16* __restrict__ Hi,
                             __nv_bfloat16* __restrict__ Lo, float scale)
{
    const int i = (blockIdx.x * blockDim.x + threadIdx.x) * 4;
    float4 v = *(const float4*)(X + i);
    __nv_bfloat16 h[4], l[4];
    split1(v.x * scale, h[0], l[0]); split1(v.y * scale, h[1], l[1]);
    split1(v.z * scale, h[2], l[2]); split1(v.w * scale, h[3], l[3]);
    *(uint2*)(Hi + i) = *(uint2*)h;
    *(uint2*)(Lo + i) = *(uint2*)l;
}

// W [K][N] fp32 -> W^T [N][K] bf16 hi/lo
__global__ void wsplit_kernel(const float* __restrict__ W,
                              __nv_bfloat16* __restrict__ Hi,
                              __nv_bfloat16* __restrict__ Lo)
{
    __shared__ float tile[32][33];
    const int n0 = blockIdx.x * 32, k0 = blockIdx.y * 32;
    const int tx = threadIdx.x, ty = threadIdx.y;   // 32 x 8
    #pragma unroll
    for (int r = 0; r < 32; r += 8)
        tile[ty + r][tx] = W[(size_t)(k0 + ty + r) * C_ + n0 + tx];
    __syncthreads();
    #pragma unroll
    for (int r = 0; r < 32; r += 8) {
        const int n = n0 + ty + r, k = k0 + tx;
        __nv_bfloat16 h, l;
        split1(tile[tx][ty + r], h, l);
        Hi[(size_t)n * C_ + k] = h;
        Lo[(size_t)n * C_ + k] = l;
    }
}

// V [bh][t][d] fp32 -> V^T [bh][d][t] bf16 hi/lo
__global__ void vtsplit_kernel(const float* __restrict__ V,
                               __nv_bfloat16* __restrict__ Hi,
                               __nv_bfloat16* __restrict__ Lo)
{
    __shared__ float tile[32][33];
    const int bh = blockIdx.z;
    const int t0 = blockIdx.x * 32, d0 = blockIdx.y * 32;
    const int tx = threadIdx.x, ty = threadIdx.y;   // 32 x 8
    const float* src = V + (size_t)bh * T_ * HD_;
    #pragma unroll
    for (int r = 0; r < 32; r += 8)
        tile[ty + r][tx] = src[(size_t)(t0 + ty + r) * HD_ + d0 + tx];
    __syncthreads();
    __nv_bfloat16* dh = Hi + (size_t)bh * HD_ * T_;
    __nv_bfloat16* dl = Lo + (size_t)bh * HD_ * T_;
    #pragma unroll
    for (int r = 0; r < 32; r += 8) {
        __nv_bfloat16 h, l;
        split1(tile[tx][ty + r], h, l);
        const size_t o = (size_t)(d0 + ty + r) * T_ + t0 + tx;
        dh[o] = h; dl[o] = l;
    }
}

// ---------------------------------------------------------------------------
// bf16-split GEMM via mma.sync (unchanged from round 4)
// ---------------------------------------------------------------------------
#define PA 40
#define HALF_OFF   10240u
#define BBASE_OFF  20480u
#define BUF_BYTES  40960u
#define GEMM_SMEM  (2 * BUF_BYTES)

__global__ __launch_bounds__(256, 2)
void gemm_tc(const __nv_bfloat16* __restrict__ Ahi, const __nv_bfloat16* __restrict__ Alo,
             const __nv_bfloat16* __restrict__ Bhi, const __nv_bfloat16* __restrict__ Blo,
             const float* __restrict__ bias, float* __restrict__ Out, int split)
{
    extern __shared__ char sm[];
    const uint32_t sbase = smem_u32(sm);
    const int tid  = threadIdx.x;
    const int lane = tid & 31;
    const int wid  = tid >> 5;
    const int wm   = wid >> 2;
    const int wn   = wid & 3;
    const int brow = blockIdx.y * 128;
    const int bcol = blockIdx.x * 128;

    const int r0 = tid >> 2, s0 = tid & 3;
    const int r1 = (tid + 256) >> 2, s1 = s0;

    float acc[4][4][4];
    #pragma unroll
    for (int mt = 0; mt < 4; mt++)
        #pragma unroll
        for (int nt = 0; nt < 4; nt++)
            #pragma unroll
            for (int e = 0; e < 4; e++) acc[mt][nt][e] = 0.f;

    auto load_chunk = [&](int kc, int buf) {
        const uint32_t d0 = sbase + buf * BUF_BYTES;
        const size_t ka = (size_t)kc * 32;
        uint32_t dA0 = d0 + r0 * 80 + s0 * 16;
        uint32_t dA1 = d0 + r1 * 80 + s1 * 16;
        cp16(dA0,              Ahi + (size_t)(brow + r0) * C_ + ka + s0 * 8);
        cp16(dA1,              Ahi + (size_t)(brow + r1) * C_ + ka + s1 * 8);
        cp16(dA0 + HALF_OFF,   Alo + (size_t)(brow + r0) * C_ + ka + s0 * 8);
        cp16(dA1 + HALF_OFF,   Alo + (size_t)(brow + r1) * C_ + ka + s1 * 8);
        cp16(dA0 + BBASE_OFF,            Bhi + (size_t)(bcol + r0) * C_ + ka + s0 * 8);
        cp16(dA1 + BBASE_OFF,            Bhi + (size_t)(bcol + r1) * C_ + ka + s1 * 8);
        cp16(dA0 + BBASE_OFF + HALF_OFF, Blo + (size_t)(bcol + r0) * C_ + ka + s0 * 8);
        cp16(dA1 + BBASE_OFF + HALF_OFF, Blo + (size_t)(bcol + r1) * C_ + ka + s1 * 8);
        CP_COMMIT();
    };

    load_chunk(0, 0);

    for (int kc = 0; kc < 32; kc++) {
        const int cur = kc & 1;
        if (kc + 1 < 32) { load_chunk(kc + 1, cur ^ 1); CP_WAIT(1); }
        else             { CP_WAIT(0); }
        __syncthreads();

        const uint32_t aB = sbase + cur * BUF_BYTES;
        const uint32_t bB = aB + BBASE_OFF;

        #pragma unroll
        for (int s = 0; s < 2; s++) {
            uint32_t bh[8], bl[8];
            #pragma unroll
            for (int p = 0; p < 2; p++) {
                const int nrow = wn * 32 + p * 16 + ((lane >> 4) & 1) * 8 + (lane & 7);
                const int col  = s * 16 + ((lane >> 3) & 1) * 8;
                const uint32_t bd = bB + (nrow * PA + col) * 2;
                ldsm_x4(&bh[p * 4], bd);
                ldsm_x4(&bl[p * 4], bd + HALF_OFF);
            }
            #pragma unroll
            for (int mt = 0; mt < 4; mt++) {
                const int arow = wm * 64 + mt * 16 + (lane & 15);
                const int acol = s * 16 + ((lane >> 4) << 3);
                const uint32_t ad = aB + (arow * PA + acol) * 2;
                uint32_t af[4];
                ldsm_x4(af, ad);
                #pragma unroll
                for (int nt = 0; nt < 4; nt++) {
                    mma_bf16(acc[mt][nt], af, &bh[nt * 2]);
                    mma_bf16(acc[mt][nt], af, &bl[nt * 2]);
                }
                ldsm_x4(af, ad + HALF_OFF);
                #pragma unroll
                for (int nt = 0; nt < 4; nt++)
                    mma_bf16(acc[mt][nt], af, &bh[nt * 2]);
            }
        }
        __syncthreads();
    }

    const int g  = lane >> 2;
    const int tg = lane & 3;
    #pragma unroll
    for (int nt = 0; nt < 4; nt++) {
        const int n = bcol + wn * 32 + nt * 8 + tg * 2;
        const float bx = bias[n], by = bias[n + 1];
        #pragma unroll
        for (int mt = 0; mt < 4; mt++) {
            const int mr0 = brow + wm * 64 + mt * 16 + g;
            const int mr1 = mr0 + 8;
            float2 v0 = make_float2(acc[mt][nt][0] + bx, acc[mt][nt][1] + by);
            float2 v1 = make_float2(acc[mt][nt][2] + bx, acc[mt][nt][3] + by);
            if (!split) {
                *(float2*)(Out + (size_t)mr0 * C_ + n) = v0;
                *(float2*)(Out + (size_t)mr1 * C_ + n) = v1;
            } else {
                const int h = n >> 6, hd = n & 63;
                const int bb0 = mr0 >> 11, t0 = mr0 & 2047;
                const int bb1 = mr1 >> 11, t1 = mr1 & 2047;
                *(float2*)(Out + (((size_t)(bb0 * H_ + h) * T_) + t0) * HD_ + hd) = v0;
                *(float2*)(Out + (((size_t)(bb1 * H_ + h) * T_) + t1) * HD_ + hd) = v1;
            }
        }
    }
}

// ---------------------------------------------------------------------------
// Flash attention via bf16-split mma.sync.
// Grid (16, 32), 256 threads = 8 warps, each warp owns m16 of the 128-row
// Q tile. K/V tiles of 64 positions, double-buffered cp.async.
// smem pitch = 144 bytes (72 bf16) -> conflict-free ldmatrix.
// ---------------------------------------------------------------------------
#define AQHI   0u
#define AQLO   18432u            // 128*144
#define ASTG0  36864u
#define ASTG_SZ 36864u           // 4 arrays * 64*144
#define AK_HI  0u
#define AK_LO  9216u             // 64*144
#define AV_HI  18432u
#define AV_LO  27648u
#define ATTN_SMEM (ASTG0 + 2 * ASTG_SZ)   // 110592

__device__ __forceinline__ uint32_t pack_split(float a, float b, uint32_t& lo) {
    __nv_bfloat16 ha = __float2bfloat16(a), hb = __float2bfloat16(b);
    float ra = a - __bfloat162float(ha);
    float rb = b - __bfloat162float(hb);
    __nv_bfloat162 Hh = __halves2bfloat162(ha, hb);
    __nv_bfloat162 Ll = __halves2bfloat162(__float2bfloat16(ra), __float2bfloat16(rb));
    lo = *(uint32_t*)&Ll;
    return *(uint32_t*)&Hh;
}

__global__ __launch_bounds__(256, 1)
void attn_mma(const __nv_bfloat16* __restrict__ Qhi, const __nv_bfloat16* __restrict__ Qlo,
              const __nv_bfloat16* __restrict__ Khi, const __nv_bfloat16* __restrict__ Klo,
              const __nv_bfloat16* __restrict__ Vthi, const __nv_bfloat16* __restrict__ Vtlo,
              float* __restrict__ Yg)
{
    extern __shared__ char sm[];
    const uint32_t sbase = smem_u32(sm);
    const int tid  = threadIdx.x;
    const int lane = tid & 31;
    const int w    = tid >> 5;
    const int g    = lane >> 2;
    const int tg   = lane & 3;

    const int qt = (int)gridDim.x - 1 - (int)blockIdx.x;   // largest first
    const int bh = blockIdx.y;
    const int qrow0 = qt * 128 + w * 16;
    const int nkt = 2 * qt + 2;

    const __nv_bfloat16* qhb = Qhi + ((size_t)bh * T_ + qt * 128) * HD_;
    const __nv_bfloat16* qlb = Qlo + ((size_t)bh * T_ + qt * 128) * HD_;
    const __nv_bfloat16* khb = Khi + (size_t)bh * T_ * HD_;
    const __nv_bfloat16* klb = Klo + (size_t)bh * T_ * HD_;
    const __nv_bfloat16* vhb = Vthi + (size_t)bh * HD_ * T_;
    const __nv_bfloat16* vlb = Vtlo + (size_t)bh * HD_ * T_;

    // --- Q stage (once) ---
    #pragma unroll
    for (int i = 0; i < 8; i++) {
        const int idx = tid + i * 256;
        const int arr = idx >> 10;              // 0:hi 1:lo
        const int row = (idx >> 3) & 127;
        const int seg = idx & 7;
        const __nv_bfloat16* src = (arr ? qlb : qhb) + (size_t)row * HD_ + seg * 8;
        cp16(sbase + arr * 18432u + row * 144 + seg * 16, src);
    }
    CP_COMMIT();

    // --- K/V tile loader ---
    auto loadKV = [&](int kt) {
        const uint32_t d0 = sbase + ASTG0 + (uint32_t)(kt & 1) * ASTG_SZ;
        #pragma unroll
        for (int i = 0; i < 8; i++) {
            const int idx = tid + i * 256;
            const int arr = idx >> 9;           // 0:Khi 1:Klo 2:Vhi 3:Vlo
            const int row = (idx >> 3) & 63;
            const int seg = idx & 7;
            const __nv_bfloat16* src;
            if (arr == 0)      src = khb + (size_t)(kt * 64 + row) * HD_ + seg * 8;
            else if (arr == 1) src = klb + (size_t)(kt * 64 + row) * HD_ + seg * 8;
            else if (arr == 2) src = vhb + (size_t)row * T_ + kt * 64 + seg * 8;
            else               src = vlb + (size_t)row * T_ + kt * 64 + seg * 8;
            cp16(d0 + arr * 9216u + row * 144 + seg * 16, src);
        }
        CP_COMMIT();
    };

    loadKV(0);
    CP_WAIT(0);
    __syncthreads();

    // --- Q fragments (held in registers for whole kernel) ---
    uint32_t qh[16], ql[16];
    #pragma unroll
    for (int s = 0; s < 4; s++) {
        const int arow = w * 16 + (lane & 15);
        const int acol = s * 16 + ((lane >> 4) << 3);
        const uint32_t qa = sbase + AQHI + arow * 144 + acol * 2;
        ldsm_x4(&qh[s * 4], qa);
        ldsm_x4(&ql[s * 4], qa + 18432u);
    }

    float m0 = -1e30f, m1 = -1e30f, l0 = 0.f, l1 = 0.f;
    float O[8][4];
    #pragma unroll
    for (int dt = 0; dt < 8; dt++)
        #pragma unroll
        for (int e = 0; e < 4; e++) O[dt][e] = 0.f;

    for (int kt = 0; kt < nkt; kt++) {
        if (kt + 1 < nkt) { loadKV(kt + 1); CP_WAIT(1); }
        else              { CP_WAIT(0); }
        __syncthreads();

        const uint32_t kb = sbase + ASTG0 + (uint32_t)(kt & 1) * ASTG_SZ;
        const bool active = (kt * 64 <= qrow0 + 15);
        if (active) {
            // ---- S = Q K^T ----
            float S[8][4];
            #pragma unroll
            for (int nt = 0; nt < 8; nt++)
                #pragma unroll
                for (int e = 0; e < 4; e++) S[nt][e] = 0.f;

            #pragma unroll
            for (int s = 0; s < 4; s++) {
                uint32_t kh[16], kl[16];
                #pragma unroll
                for (int p = 0; p < 4; p++) {
                    const int nrow = p * 16 + ((lane >> 4) & 1) * 8 + (lane & 7);
                    const int col  = s * 16 + ((lane >> 3) & 1) * 8;
                    const uint32_t ad = kb + AK_HI + nrow * 144 + col * 2;
                    ldsm_x4(&kh[p * 4], ad);
                    ldsm_x4(&kl[p * 4], ad + 9216u);
                }
                #pragma unroll
                for (int nt = 0; nt < 8; nt++) {
                    mma_bf16(S[nt], &qh[s * 4], &kh[nt * 2]);
                    mma_bf16(S[nt], &qh[s * 4], &kl[nt * 2]);
                    mma_bf16(S[nt], &ql[s * 4], &kh[nt * 2]);
                }
            }

            // ---- causal mask ----
            if (kt * 64 + 63 > qrow0) {
                const int r0 = qrow0 + g, r1 = r0 + 8;
                const int cbase = kt * 64 + 2 * tg;
                #pragma unroll
                for (int nt = 0; nt < 8; nt++) {
                    const int c0 = cbase + nt * 8;
                    if (c0     > r0) S[nt][0] = -1e30f;
                    if (c0 + 1 > r0) S[nt][1] = -1e30f;
                    if (c0     > r1) S[nt][2] = -1e30f;
                    if (c0 + 1 > r1) S[nt][3] = -1e30f;
                }
            }

            // ---- online softmax ----
            float mx0 = -1e30f, mx1 = -1e30f;
            #pragma unroll
            for (int nt = 0; nt < 8; nt++) {
                mx0 = fmaxf(mx0, fmaxf(S[nt][0], S[nt][1]));
                mx1 = fmaxf(mx1, fmaxf(S[nt][2], S[nt][3]));
            }
            mx0 = fmaxf(mx0, __shfl_xor_sync(0xffffffffu, mx0, 1));
            mx0 = fmaxf(mx0, __shfl_xor_sync(0xffffffffu, mx0, 2));
            mx1 = fmaxf(mx1, __shfl_xor_sync(0xffffffffu, mx1, 1));
            mx1 = fmaxf(mx1, __shfl_xor_sync(0xffffffffu, mx1, 2));
            const float nm0 = fmaxf(m0, mx0), nm1 = fmaxf(m1, mx1);
            const float corr0 = __expf(m0 - nm0), corr1 = __expf(m1 - nm1);
            m0 = nm0; m1 = nm1;

            float s0 = 0.f, s1 = 0.f;
            uint32_t phi[16], plo[16];
            #pragma unroll
            for (int nt = 0; nt < 8; nt++) {
                const float p0 = __expf(S[nt][0] - m0);
                const float p1 = __expf(S[nt][1] - m0);
                const float p2 = __expf(S[nt][2] - m1);
                const float p3 = __expf(S[nt][3] - m1);
                s0 += p0 + p1; s1 += p2 + p3;
                const int bi = (nt >> 1) * 4 + (nt & 1) * 2;
                phi[bi]     = pack_split(p0, p1, plo[bi]);
                phi[bi + 1] = pack_split(p2, p3, plo[bi + 1]);
            }
            s0 += __shfl_xor_sync(0xffffffffu, s0, 1);
            s0 += __shfl_xor_sync(0xffffffffu, s0, 2);
            s1 += __shfl_xor_sync(0xffffffffu, s1, 1);
            s1 += __shfl_xor_sync(0xffffffffu, s1, 2);
            l0 = l0 * corr0 + s0;
            l1 = l1 * corr1 + s1;

            #pragma unroll
            for (int dt = 0; dt < 8; dt++) {
                O[dt][0] *= corr0; O[dt][1] *= corr0;
                O[dt][2] *= corr1; O[dt][3] *= corr1;
            }

            // ---- O += P V ----
            #pragma unroll
            for (int j = 0; j < 4; j++) {
                uint32_t vh[16], vl[16];
                #pragma unroll
                for (int p = 0; p < 4; p++) {
                    const int nrow = p * 16 + ((lane >> 4) & 1) * 8 + (lane & 7);
                    const int col  = j * 16 + ((lane >> 3) & 1) * 8;
                    const uint32_t ad = kb + AV_HI + nrow * 144 + col * 2;
                    ldsm_x4(&vh[p * 4], ad);
                    ldsm_x4(&vl[p * 4], ad + 9216u);
                }
                #pragma unroll
                for (int dt = 0; dt < 8; dt++) {
                    mma_bf16(O[dt], &phi[j * 4], &vh[dt * 2]);
                    mma_bf16(O[dt], &phi[j * 4], &vl[dt * 2]);
                    mma_bf16(O[dt], &plo[j * 4], &vh[dt * 2]);
                }
            }
        }
        __syncthreads();
    }

    // ---- epilogue: normalize and write y [B,T,C] ----
    const float inv0 = 1.0f / l0, inv1 = 1.0f / l1;
    const int bb = bh >> 4, h = bh & 15;
    const int t0 = qrow0 + g, t1 = t0 + 8;
    #pragma unroll
    for (int dt = 0; dt < 8; dt++) {
        const int col = h * 64 + dt * 8 + 2 * tg;
        float2 v0 = make_float2(O[dt][0] * inv0, O[dt][1] * inv0);
        float2 v1 = make_float2(O[dt][2] * inv1, O[dt][3] * inv1);
        *(float2*)(Yg + ((size_t)(bb * T_ + t0)) * C_ + col) = v0;
        *(float2*)(Yg + ((size_t)(bb * T_ + t1)) * C_ + col) = v1;
    }
}

// ---------------------------------------------------------------------------
extern "C" void kernel_launch(void* const* d_in, const int* in_sizes, int n_in,
                              void* d_out, int out_size)
{
    const float* query = (const float*)d_in[0];
    const float* key   = (const float*)d_in[1];
    const float* value = (const float*)d_in[2];
    // d_in[3] = att_mask (causal tril; provably unused)
    const float* Wq = (const float*)d_in[4];
    const float* bq = (const float*)d_in[5];
    const float* Wk = (const float*)d_in[6];
    const float* bk = (const float*)d_in[7];
    const float* Wv = (const float*)d_in[8];
    const float* bv = (const float*)d_in[9];
    const float* Wp = (const float*)d_in[10];
    const float* bp = (const float*)d_in[11];
    float* out = (float*)d_out;

    float *gq, *gk, *gv, *gy;
    __nv_bfloat16 *ahi, *alo, *whi, *wlo;
    __nv_bfloat16 *qhi, *qlo, *khi, *klo, *vthi, *vtlo;
    cudaGetSymbolAddress((void**)&gq, g_q);
    cudaGetSymbolAddress((void**)&gk, g_k);
    cudaGetSymbolAddress((void**)&gv, g_v);
    cudaGetSymbolAddress((void**)&gy, g_y);
    cudaGetSymbolAddress((void**)&ahi, g_ahi);
    cudaGetSymbolAddress((void**)&alo, g_alo);
    cudaGetSymbolAddress((void**)&whi, g_whi);
    cudaGetSymbolAddress((void**)&wlo, g_wlo);
    cudaGetSymbolAddress((void**)&qhi, g_qhi);
    cudaGetSymbolAddress((void**)&qlo, g_qlo);
    cudaGetSymbolAddress((void**)&khi, g_khi);
    cudaGetSymbolAddress((void**)&klo, g_klo);
    cudaGetSymbolAddress((void**)&vthi, g_vthi);
    cudaGetSymbolAddress((void**)&vtlo, g_vtlo);

    cudaFuncSetAttribute(gemm_tc,
                         cudaFuncAttributeMaxDynamicSharedMemorySize, GEMM_SMEM);
    cudaFuncSetAttribute(attn_mma,
                         cudaFuncAttributeMaxDynamicSharedMemorySize, ATTN_SMEM);

    const int SPLIT_BLK = 256;
    const int nsplit = (M_ * C_) / (SPLIT_BLK * 4);
    dim3 wgrid(C_ / 32, C_ / 32), wblk(32, 8);
    dim3 ggrid(C_ / 128, M_ / 128);   // (8, 32)

    // QKV projections (fp32 outputs in head-split layout)
    split_kernel<<<nsplit, SPLIT_BLK>>>(query, ahi, alo, 1.0f);
    wsplit_kernel<<<wgrid, wblk>>>(Wq, whi, wlo);
    gemm_tc<<<ggrid, 256, GEMM_SMEM>>>(ahi, alo, whi, wlo, bq, gq, 1);

    split_kernel<<<nsplit, SPLIT_BLK>>>(key, ahi, alo, 1.0f);
    wsplit_kernel<<<wgrid, wblk>>>(Wk, whi, wlo);
    gemm_tc<<<ggrid, 256, GEMM_SMEM>>>(ahi, alo, whi, wlo, bk, gk, 1);

    split_kernel<<<nsplit, SPLIT_BLK>>>(value, ahi, alo, 1.0f);
    wsplit_kernel<<<wgrid, wblk>>>(Wv, whi, wlo);
    gemm_tc<<<ggrid, 256, GEMM_SMEM>>>(ahi, alo, whi, wlo, bv, gv, 1);

    // attention operand splits
    split_kernel<<<nsplit, SPLIT_BLK>>>(gq, qhi, qlo, SM_SCALE);
    split_kernel<<<nsplit, SPLIT_BLK>>>(gk, khi, klo, 1.0f);
    vtsplit_kernel<<<dim3(T_ / 32, HD_ / 32, BH_), wblk>>>(gv, vthi, vtlo);

    // flash attention (tensor cores)
    attn_mma<<<dim3(T_ / 128, BH_), 256, ATTN_SMEM>>>(qhi, qlo, khi, klo,
                                                      vthi, vtlo, gy);

    // output projection
    split_kernel<<<nsplit, SPLIT_BLK>>>(gy, ahi, alo, 1.0f);
    wsplit_kernel<<<wgrid, wblk>>>(Wp, whi, wlo);
    gemm_tc<<<ggrid, 256, GEMM_SMEM>>>(ahi, alo, whi, wlo, bp, out, 0);
}

// round 6
// speedup vs baseline: 3.0325x; 1.0137x over previous
#include <cuda_runtime.h>
#include <cuda_bf16.h>
#include <cstdint>

// Problem constants
#define B_   2
#define T_   2048
#define C_   1024
#define H_   16
#define HD_  64
#define M_   (B_*T_)    // 4096
#define BH_  (B_*H_)    // 32
#define SM_SCALE 0.125f // 1/sqrt(64)

// ---------------------------------------------------------------------------
// Scratch (device globals: allocation-guard safe)
// ---------------------------------------------------------------------------
__device__ __nv_bfloat16 g_inhi[(size_t)3*M_*C_];   // split inputs q,k,v
__device__ __nv_bfloat16 g_inlo[(size_t)3*M_*C_];
__device__ __nv_bfloat16 g_whi[(size_t)4*C_*C_];    // W^T [4][N][K]
__device__ __nv_bfloat16 g_wlo[(size_t)4*C_*C_];
__device__ __nv_bfloat16 g_qhi[(size_t)BH_*T_*HD_];
__device__ __nv_bfloat16 g_qlo[(size_t)BH_*T_*HD_];
__device__ __nv_bfloat16 g_khi[(size_t)BH_*T_*HD_];
__device__ __nv_bfloat16 g_klo[(size_t)BH_*T_*HD_];
__device__ __nv_bfloat16 g_vhi[(size_t)BH_*T_*HD_];
__device__ __nv_bfloat16 g_vlo[(size_t)BH_*T_*HD_];
__device__ __nv_bfloat16 g_vthi[(size_t)BH_*HD_*T_];  // transposed [bh][d][t]
__device__ __nv_bfloat16 g_vtlo[(size_t)BH_*HD_*T_];
__device__ __nv_bfloat16 g_yhi[(size_t)M_*C_];
__device__ __nv_bfloat16 g_ylo[(size_t)M_*C_];

// ---------------------------------------------------------------------------
// Base-target PTX helpers
// ---------------------------------------------------------------------------
__device__ __forceinline__ uint32_t smem_u32(const void* p) {
    uint32_t a;
    asm("{ .reg .u64 t; cvta.to.shared.u64 t, %1; cvt.u32.u64 %0, t; }"
        : "=r"(a) : "l"(p));
    return a;
}
__device__ __forceinline__ void cp16(uint32_t dst, const void* src) {
    asm volatile("{ .reg .u64 g; cvta.to.global.u64 g, %1;"
                 "  cp.async.cg.shared.global [%0], [g], 16; }"
                 :: "r"(dst), "l"(src) : "memory");
}
#define CP_COMMIT() asm volatile("cp.async.commit_group;" ::: "memory")
#define CP_WAIT(N)  asm volatile("cp.async.wait_group %0;" :: "n"(N) : "memory")

__device__ __forceinline__ void ldsm_x4(uint32_t* r, uint32_t addr) {
    asm volatile("ldmatrix.sync.aligned.m8n8.x4.shared.b16 {%0,%1,%2,%3}, [%4];"
                 : "=r"(r[0]), "=r"(r[1]), "=r"(r[2]), "=r"(r[3]) : "r"(addr));
}
__device__ __forceinline__ void mma_bf16(float* c, const uint32_t* a, const uint32_t* b) {
    asm volatile(
        "mma.sync.aligned.m16n8k16.row.col.f32.bf16.bf16.f32 "
        "{%0,%1,%2,%3}, {%4,%5,%6,%7}, {%8,%9}, {%0,%1,%2,%3};"
        : "+f"(c[0]), "+f"(c[1]), "+f"(c[2]), "+f"(c[3])
        : "r"(a[0]), "r"(a[1]), "r"(a[2]), "r"(a[3]), "r"(b[0]), "r"(b[1]));
}

__device__ __forceinline__ void split1(float v, __nv_bfloat16& h, __nv_bfloat16& l) {
    h = __float2bfloat16(v);
    l = __float2bfloat16(v - __bfloat162float(h));
}
__device__ __forceinline__ uint32_t pack_split(float a, float b, uint32_t& lo) {
    __nv_bfloat16 ha = __float2bfloat16(a), hb = __float2bfloat16(b);
    float ra = a - __bfloat162float(ha);
    float rb = b - __bfloat162float(hb);
    __nv_bfloat162 Hh = __halves2bfloat162(ha, hb);
    __nv_bfloat162 Ll = __halves2bfloat162(__float2bfloat16(ra), __float2bfloat16(rb));
    lo = *(uint32_t*)&Ll;
    return *(uint32_t*)&Hh;
}

// ---------------------------------------------------------------------------
// Conversion kernels
// ---------------------------------------------------------------------------
// 3 inputs -> concatenated hi/lo
__global__ void split3_kernel(const float* __restrict__ Q, const float* __restrict__ K,
                              const float* __restrict__ V,
                              __nv_bfloat16* __restrict__ Hi,
                              __nv_bfloat16* __restrict__ Lo)
{
    const int z = blockIdx.y;
    const float* X = (z == 0) ? Q : (z == 1) ? K : V;
    const size_t off = (size_t)z * M_ * C_;
    const int i = (blockIdx.x * blockDim.x + threadIdx.x) * 4;
    float4 v = *(const float4*)(X + i);
    __nv_bfloat16 h[4], l[4];
    split1(v.x, h[0], l[0]); split1(v.y, h[1], l[1]);
    split1(v.z, h[2], l[2]); split1(v.w, h[3], l[3]);
    *(uint2*)(Hi + off + i) = *(uint2*)h;
    *(uint2*)(Lo + off + i) = *(uint2*)l;
}

// 4 weights [K][N] fp32 -> W^T [z][N][K] bf16 hi/lo
__global__ void wsplit4_kernel(const float* __restrict__ W0, const float* __restrict__ W1,
                               const float* __restrict__ W2, const float* __restrict__ W3,
                               __nv_bfloat16* __restrict__ Hi,
                               __nv_bfloat16* __restrict__ Lo)
{
    __shared__ float tile[32][33];
    const int z = blockIdx.z;
    const float* W = (z == 0) ? W0 : (z == 1) ? W1 : (z == 2) ? W2 : W3;
    const size_t off = (size_t)z * C_ * C_;
    const int n0 = blockIdx.x * 32, k0 = blockIdx.y * 32;
    const int tx = threadIdx.x, ty = threadIdx.y;   // 32 x 8
    #pragma unroll
    for (int r = 0; r < 32; r += 8)
        tile[ty + r][tx] = W[(size_t)(k0 + ty + r) * C_ + n0 + tx];
    __syncthreads();
    #pragma unroll
    for (int r = 0; r < 32; r += 8) {
        const int n = n0 + ty + r, k = k0 + tx;
        __nv_bfloat16 h, l;
        split1(tile[tx][ty + r], h, l);
        Hi[off + (size_t)n * C_ + k] = h;
        Lo[off + (size_t)n * C_ + k] = l;
    }
}

// V [bh][t][d] bf16 hi/lo -> V^T [bh][d][t] bf16 hi/lo (exact move)
__global__ void vtrans_kernel(const __nv_bfloat16* __restrict__ Vhi,
                              const __nv_bfloat16* __restrict__ Vlo,
                              __nv_bfloat16* __restrict__ Thi,
                              __nv_bfloat16* __restrict__ Tlo)
{
    __shared__ __nv_bfloat16 th[32][33], tl[32][33];
    const int bh = blockIdx.z;
    const int t0 = blockIdx.x * 32, d0 = blockIdx.y * 32;
    const int tx = threadIdx.x, ty = threadIdx.y;   // 32 x 8
    const __nv_bfloat16* sh = Vhi + (size_t)bh * T_ * HD_;
    const __nv_bfloat16* sl = Vlo + (size_t)bh * T_ * HD_;
    #pragma unroll
    for (int r = 0; r < 32; r += 8) {
        th[ty + r][tx] = sh[(size_t)(t0 + ty + r) * HD_ + d0 + tx];
        tl[ty + r][tx] = sl[(size_t)(t0 + ty + r) * HD_ + d0 + tx];
    }
    __syncthreads();
    __nv_bfloat16* dh = Thi + (size_t)bh * HD_ * T_;
    __nv_bfloat16* dl = Tlo + (size_t)bh * HD_ * T_;
    #pragma unroll
    for (int r = 0; r < 32; r += 8) {
        const size_t o = (size_t)(d0 + ty + r) * T_ + t0 + tx;
        dh[o] = th[tx][ty + r];
        dl[o] = tl[tx][ty + r];
    }
}

// ---------------------------------------------------------------------------
// Shared GEMM mainloop: 128x128 tile, BK=32, double-buffered cp.async,
// bf16 hi/lo 3-product accumulation.
// ---------------------------------------------------------------------------
#define PA 40
#define HALF_OFF   10240u
#define BBASE_OFF  20480u
#define BUF_BYTES  40960u
#define GEMM_SMEM  (2 * BUF_BYTES)

static __device__ __forceinline__ void gemm_mainloop(
    const __nv_bfloat16* __restrict__ Ahi, const __nv_bfloat16* __restrict__ Alo,
    const __nv_bfloat16* __restrict__ Bhi, const __nv_bfloat16* __restrict__ Blo,
    uint32_t sbase, int brow, int bcol, int tid, float acc[4][4][4])
{
    const int lane = tid & 31;
    const int wid  = tid >> 5;
    const int wm   = wid >> 2;
    const int wn   = wid & 3;
    const int r0 = tid >> 2, s0 = tid & 3;
    const int r1 = (tid + 256) >> 2;

    auto load_chunk = [&](int kc, int buf) {
        const uint32_t d0 = sbase + buf * BUF_BYTES;
        const size_t ka = (size_t)kc * 32;
        uint32_t dA0 = d0 + r0 * 80 + s0 * 16;
        uint32_t dA1 = d0 + r1 * 80 + s0 * 16;
        cp16(dA0,              Ahi + (size_t)(brow + r0) * C_ + ka + s0 * 8);
        cp16(dA1,              Ahi + (size_t)(brow + r1) * C_ + ka + s0 * 8);
        cp16(dA0 + HALF_OFF,   Alo + (size_t)(brow + r0) * C_ + ka + s0 * 8);
        cp16(dA1 + HALF_OFF,   Alo + (size_t)(brow + r1) * C_ + ka + s0 * 8);
        cp16(dA0 + BBASE_OFF,            Bhi + (size_t)(bcol + r0) * C_ + ka + s0 * 8);
        cp16(dA1 + BBASE_OFF,            Bhi + (size_t)(bcol + r1) * C_ + ka + s0 * 8);
        cp16(dA0 + BBASE_OFF + HALF_OFF, Blo + (size_t)(bcol + r0) * C_ + ka + s0 * 8);
        cp16(dA1 + BBASE_OFF + HALF_OFF, Blo + (size_t)(bcol + r1) * C_ + ka + s0 * 8);
        CP_COMMIT();
    };

    load_chunk(0, 0);

    for (int kc = 0; kc < 32; kc++) {
        const int cur = kc & 1;
        if (kc + 1 < 32) { load_chunk(kc + 1, cur ^ 1); CP_WAIT(1); }
        else             { CP_WAIT(0); }
        __syncthreads();

        const uint32_t aB = sbase + cur * BUF_BYTES;
        const uint32_t bB = aB + BBASE_OFF;

        #pragma unroll
        for (int s = 0; s < 2; s++) {
            uint32_t bh[8], bl[8];
            #pragma unroll
            for (int p = 0; p < 2; p++) {
                const int nrow = wn * 32 + p * 16 + ((lane >> 4) & 1) * 8 + (lane & 7);
                const int col  = s * 16 + ((lane >> 3) & 1) * 8;
                const uint32_t bd = bB + (nrow * PA + col) * 2;
                ldsm_x4(&bh[p * 4], bd);
                ldsm_x4(&bl[p * 4], bd + HALF_OFF);
            }
            #pragma unroll
            for (int mt = 0; mt < 4; mt++) {
                const int arow = wm * 64 + mt * 16 + (lane & 15);
                const int acol = s * 16 + ((lane >> 4) << 3);
                const uint32_t ad = aB + (arow * PA + acol) * 2;
                uint32_t af[4];
                ldsm_x4(af, ad);
                #pragma unroll
                for (int nt = 0; nt < 4; nt++) {
                    mma_bf16(acc[mt][nt], af, &bh[nt * 2]);
                    mma_bf16(acc[mt][nt], af, &bl[nt * 2]);
                }
                ldsm_x4(af, ad + HALF_OFF);
                #pragma unroll
                for (int nt = 0; nt < 4; nt++)
                    mma_bf16(acc[mt][nt], af, &bh[nt * 2]);
            }
        }
        __syncthreads();
    }
}

// ---------------------------------------------------------------------------
// Fused QKV projection GEMM: grid (8, 32, 3). Outputs bf16 hi/lo head-split.
// ---------------------------------------------------------------------------
__global__ __launch_bounds__(256, 2)
void gemm_qkv(const __nv_bfloat16* __restrict__ Inhi, const __nv_bfloat16* __restrict__ Inlo,
              const __nv_bfloat16* __restrict__ Whi, const __nv_bfloat16* __restrict__ Wlo,
              const float* __restrict__ bq, const float* __restrict__ bk,
              const float* __restrict__ bv,
              __nv_bfloat16* __restrict__ Qhi, __nv_bfloat16* __restrict__ Qlo,
              __nv_bfloat16* __restrict__ Khi, __nv_bfloat16* __restrict__ Klo,
              __nv_bfloat16* __restrict__ Vhi, __nv_bfloat16* __restrict__ Vlo)
{
    extern __shared__ char sm[];
    const uint32_t sbase = smem_u32(sm);
    const int tid  = threadIdx.x;
    const int z    = blockIdx.z;
    const int brow = blockIdx.y * 128;
    const int bcol = blockIdx.x * 128;

    const __nv_bfloat16* Ahi = Inhi + (size_t)z * M_ * C_;
    const __nv_bfloat16* Alo = Inlo + (size_t)z * M_ * C_;
    const __nv_bfloat16* Bh  = Whi + (size_t)z * C_ * C_;
    const __nv_bfloat16* Bl  = Wlo + (size_t)z * C_ * C_;
    const float* bias = (z == 0) ? bq : (z == 1) ? bk : bv;
    __nv_bfloat16* Dhi = (z == 0) ? Qhi : (z == 1) ? Khi : Vhi;
    __nv_bfloat16* Dlo = (z == 0) ? Qlo : (z == 1) ? Klo : Vlo;
    const float scale = (z == 0) ? SM_SCALE : 1.0f;

    float acc[4][4][4];
    #pragma unroll
    for (int mt = 0; mt < 4; mt++)
        #pragma unroll
        for (int nt = 0; nt < 4; nt++)
            #pragma unroll
            for (int e = 0; e < 4; e++) acc[mt][nt][e] = 0.f;

    gemm_mainloop(Ahi, Alo, Bh, Bl, sbase, brow, bcol, tid, acc);

    const int lane = tid & 31;
    const int wid  = tid >> 5;
    const int wm   = wid >> 2, wn = wid & 3;
    const int g  = lane >> 2;
    const int tg = lane & 3;
    #pragma unroll
    for (int nt = 0; nt < 4; nt++) {
        const int n = bcol + wn * 32 + nt * 8 + tg * 2;
        const float bx = bias[n], by = bias[n + 1];
        const int h = n >> 6, hd = n & 63;
        #pragma unroll
        for (int mt = 0; mt < 4; mt++) {
            const int mr0 = brow + wm * 64 + mt * 16 + g;
            const int mr1 = mr0 + 8;
            const int bb0 = mr0 >> 11, t0 = mr0 & 2047;
            const int bb1 = mr1 >> 11, t1 = mr1 & 2047;
            uint32_t lo0, lo1;
            const uint32_t hi0 = pack_split((acc[mt][nt][0] + bx) * scale,
                                            (acc[mt][nt][1] + by) * scale, lo0);
            const uint32_t hi1 = pack_split((acc[mt][nt][2] + bx) * scale,
                                            (acc[mt][nt][3] + by) * scale, lo1);
            const size_t o0 = (((size_t)(bb0 * H_ + h) * T_) + t0) * HD_ + hd;
            const size_t o1 = (((size_t)(bb1 * H_ + h) * T_) + t1) * HD_ + hd;
            *(uint32_t*)(Dhi + o0) = hi0;
            *(uint32_t*)(Dlo + o0) = lo0;
            *(uint32_t*)(Dhi + o1) = hi1;
            *(uint32_t*)(Dlo + o1) = lo1;
        }
    }
}

// ---------------------------------------------------------------------------
// Output projection GEMM: y(hi/lo) @ Wp + bp -> fp32 out
// ---------------------------------------------------------------------------
__global__ __launch_bounds__(256, 2)
void gemm_out(const __nv_bfloat16* __restrict__ Yhi, const __nv_bfloat16* __restrict__ Ylo,
              const __nv_bfloat16* __restrict__ Whi, const __nv_bfloat16* __restrict__ Wlo,
              const float* __restrict__ bias, float* __restrict__ Out)
{
    extern __shared__ char sm[];
    const uint32_t sbase = smem_u32(sm);
    const int tid  = threadIdx.x;
    const int brow = blockIdx.y * 128;
    const int bcol = blockIdx.x * 128;

    float acc[4][4][4];
    #pragma unroll
    for (int mt = 0; mt < 4; mt++)
        #pragma unroll
        for (int nt = 0; nt < 4; nt++)
            #pragma unroll
            for (int e = 0; e < 4; e++) acc[mt][nt][e] = 0.f;

    gemm_mainloop(Yhi, Ylo, Whi, Wlo, sbase, brow, bcol, tid, acc);

    const int lane = tid & 31;
    const int wid  = tid >> 5;
    const int wm   = wid >> 2, wn = wid & 3;
    const int g  = lane >> 2;
    const int tg = lane & 3;
    #pragma unroll
    for (int nt = 0; nt < 4; nt++) {
        const int n = bcol + wn * 32 + nt * 8 + tg * 2;
        const float bx = bias[n], by = bias[n + 1];
        #pragma unroll
        for (int mt = 0; mt < 4; mt++) {
            const int mr0 = brow + wm * 64 + mt * 16 + g;
            const int mr1 = mr0 + 8;
            *(float2*)(Out + (size_t)mr0 * C_ + n) =
                make_float2(acc[mt][nt][0] + bx, acc[mt][nt][1] + by);
            *(float2*)(Out + (size_t)mr1 * C_ + n) =
                make_float2(acc[mt][nt][2] + bx, acc[mt][nt][3] + by);
        }
    }
}

// ---------------------------------------------------------------------------
// Flash attention via bf16-split mma.sync (epilogue now emits bf16 hi/lo y)
// ---------------------------------------------------------------------------
#define AQHI   0u
#define AQLO   18432u            // 128*144
#define ASTG0  36864u
#define ASTG_SZ 36864u           // 4 arrays * 64*144
#define AK_HI  0u
#define AV_HI  18432u
#define ATTN_SMEM (ASTG0 + 2 * ASTG_SZ)   // 110592

__global__ __launch_bounds__(256, 1)
void attn_mma(const __nv_bfloat16* __restrict__ Qhi, const __nv_bfloat16* __restrict__ Qlo,
              const __nv_bfloat16* __restrict__ Khi, const __nv_bfloat16* __restrict__ Klo,
              const __nv_bfloat16* __restrict__ Vthi, const __nv_bfloat16* __restrict__ Vtlo,
              __nv_bfloat16* __restrict__ Yhi, __nv_bfloat16* __restrict__ Ylo)
{
    extern __shared__ char sm[];
    const uint32_t sbase = smem_u32(sm);
    const int tid  = threadIdx.x;
    const int lane = tid & 31;
    const int w    = tid >> 5;
    const int g    = lane >> 2;
    const int tg   = lane & 3;

    const int qt = (int)gridDim.x - 1 - (int)blockIdx.x;   // largest first
    const int bh = blockIdx.y;
    const int qrow0 = qt * 128 + w * 16;
    const int nkt = 2 * qt + 2;

    const __nv_bfloat16* qhb = Qhi + ((size_t)bh * T_ + qt * 128) * HD_;
    const __nv_bfloat16* qlb = Qlo + ((size_t)bh * T_ + qt * 128) * HD_;
    const __nv_bfloat16* khb = Khi + (size_t)bh * T_ * HD_;
    const __nv_bfloat16* klb = Klo + (size_t)bh * T_ * HD_;
    const __nv_bfloat16* vhb = Vthi + (size_t)bh * HD_ * T_;
    const __nv_bfloat16* vlb = Vtlo + (size_t)bh * HD_ * T_;

    // --- Q stage (once) ---
    #pragma unroll
    for (int i = 0; i < 8; i++) {
        const int idx = tid + i * 256;
        const int arr = idx >> 10;
        const int row = (idx >> 3) & 127;
        const int seg = idx & 7;
        const __nv_bfloat16* src = (arr ? qlb : qhb) + (size_t)row * HD_ + seg * 8;
        cp16(sbase + arr * 18432u + row * 144 + seg * 16, src);
    }
    CP_COMMIT();

    auto loadKV = [&](int kt) {
        const uint32_t d0 = sbase + ASTG0 + (uint32_t)(kt & 1) * ASTG_SZ;
        #pragma unroll
        for (int i = 0; i < 8; i++) {
            const int idx = tid + i * 256;
            const int arr = idx >> 9;
            const int row = (idx >> 3) & 63;
            const int seg = idx & 7;
            const __nv_bfloat16* src;
            if (arr == 0)      src = khb + (size_t)(kt * 64 + row) * HD_ + seg * 8;
            else if (arr == 1) src = klb + (size_t)(kt * 64 + row) * HD_ + seg * 8;
            else if (arr == 2) src = vhb + (size_t)row * T_ + kt * 64 + seg * 8;
            else               src = vlb + (size_t)row * T_ + kt * 64 + seg * 8;
            cp16(d0 + arr * 9216u + row * 144 + seg * 16, src);
        }
        CP_COMMIT();
    };

    loadKV(0);
    CP_WAIT(0);
    __syncthreads();

    uint32_t qh[16], ql[16];
    #pragma unroll
    for (int s = 0; s < 4; s++) {
        const int arow = w * 16 + (lane & 15);
        const int acol = s * 16 + ((lane >> 4) << 3);
        const uint32_t qa = sbase + AQHI + arow * 144 + acol * 2;
        ldsm_x4(&qh[s * 4], qa);
        ldsm_x4(&ql[s * 4], qa + 18432u);
    }

    float m0 = -1e30f, m1 = -1e30f, l0 = 0.f, l1 = 0.f;
    float O[8][4];
    #pragma unroll
    for (int dt = 0; dt < 8; dt++)
        #pragma unroll
        for (int e = 0; e < 4; e++) O[dt][e] = 0.f;

    for (int kt = 0; kt < nkt; kt++) {
        if (kt + 1 < nkt) { loadKV(kt + 1); CP_WAIT(1); }
        else              { CP_WAIT(0); }
        __syncthreads();

        const uint32_t kb = sbase + ASTG0 + (uint32_t)(kt & 1) * ASTG_SZ;
        const bool active = (kt * 64 <= qrow0 + 15);
        if (active) {
            float S[8][4];
            #pragma unroll
            for (int nt = 0; nt < 8; nt++)
                #pragma unroll
                for (int e = 0; e < 4; e++) S[nt][e] = 0.f;

            #pragma unroll
            for (int s = 0; s < 4; s++) {
                uint32_t kh[16], kl[16];
                #pragma unroll
                for (int p = 0; p < 4; p++) {
                    const int nrow = p * 16 + ((lane >> 4) & 1) * 8 + (lane & 7);
                    const int col  = s * 16 + ((lane >> 3) & 1) * 8;
                    const uint32_t ad = kb + AK_HI + nrow * 144 + col * 2;
                    ldsm_x4(&kh[p * 4], ad);
                    ldsm_x4(&kl[p * 4], ad + 9216u);
                }
                #pragma unroll
                for (int nt = 0; nt < 8; nt++) {
                    mma_bf16(S[nt], &qh[s * 4], &kh[nt * 2]);
                    mma_bf16(S[nt], &qh[s * 4], &kl[nt * 2]);
                    mma_bf16(S[nt], &ql[s * 4], &kh[nt * 2]);
                }
            }

            if (kt * 64 + 63 > qrow0) {
                const int r0 = qrow0 + g, r1 = r0 + 8;
                const int cbase = kt * 64 + 2 * tg;
                #pragma unroll
                for (int nt = 0; nt < 8; nt++) {
                    const int c0 = cbase + nt * 8;
                    if (c0     > r0) S[nt][0] = -1e30f;
                    if (c0 + 1 > r0) S[nt][1] = -1e30f;
                    if (c0     > r1) S[nt][2] = -1e30f;
                    if (c0 + 1 > r1) S[nt][3] = -1e30f;
                }
            }

            float mx0 = -1e30f, mx1 = -1e30f;
            #pragma unroll
            for (int nt = 0; nt < 8; nt++) {
                mx0 = fmaxf(mx0, fmaxf(S[nt][0], S[nt][1]));
                mx1 = fmaxf(mx1, fmaxf(S[nt][2], S[nt][3]));
            }
            mx0 = fmaxf(mx0, __shfl_xor_sync(0xffffffffu, mx0, 1));
            mx0 = fmaxf(mx0, __shfl_xor_sync(0xffffffffu, mx0, 2));
            mx1 = fmaxf(mx1, __shfl_xor_sync(0xffffffffu, mx1, 1));
            mx1 = fmaxf(mx1, __shfl_xor_sync(0xffffffffu, mx1, 2));
            const float nm0 = fmaxf(m0, mx0), nm1 = fmaxf(m1, mx1);
            const float corr0 = __expf(m0 - nm0), corr1 = __expf(m1 - nm1);
            m0 = nm0; m1 = nm1;

            float s0 = 0.f, s1 = 0.f;
            uint32_t phi[16], plo[16];
            #pragma unroll
            for (int nt = 0; nt < 8; nt++) {
                const float p0 = __expf(S[nt][0] - m0);
                const float p1 = __expf(S[nt][1] - m0);
                const float p2 = __expf(S[nt][2] - m1);
                const float p3 = __expf(S[nt][3] - m1);
                s0 += p0 + p1; s1 += p2 + p3;
                const int bi = (nt >> 1) * 4 + (nt & 1) * 2;
                phi[bi]     = pack_split(p0, p1, plo[bi]);
                phi[bi + 1] = pack_split(p2, p3, plo[bi + 1]);
            }
            s0 += __shfl_xor_sync(0xffffffffu, s0, 1);
            s0 += __shfl_xor_sync(0xffffffffu, s0, 2);
            s1 += __shfl_xor_sync(0xffffffffu, s1, 1);
            s1 += __shfl_xor_sync(0xffffffffu, s1, 2);
            l0 = l0 * corr0 + s0;
            l1 = l1 * corr1 + s1;

            #pragma unroll
            for (int dt = 0; dt < 8; dt++) {
                O[dt][0] *= corr0; O[dt][1] *= corr0;
                O[dt][2] *= corr1; O[dt][3] *= corr1;
            }

            #pragma unroll
            for (int j = 0; j < 4; j++) {
                uint32_t vh[16], vl[16];
                #pragma unroll
                for (int p = 0; p < 4; p++) {
                    const int nrow = p * 16 + ((lane >> 4) & 1) * 8 + (lane & 7);
                    const int col  = j * 16 + ((lane >> 3) & 1) * 8;
                    const uint32_t ad = kb + AV_HI + nrow * 144 + col * 2;
                    ldsm_x4(&vh[p * 4], ad);
                    ldsm_x4(&vl[p * 4], ad + 9216u);
                }
                #pragma unroll
                for (int dt = 0; dt < 8; dt++) {
                    mma_bf16(O[dt], &phi[j * 4], &vh[dt * 2]);
                    mma_bf16(O[dt], &phi[j * 4], &vl[dt * 2]);
                    mma_bf16(O[dt], &plo[j * 4], &vh[dt * 2]);
                }
            }
        }
        __syncthreads();
    }

    // ---- epilogue: normalize and write y hi/lo bf16 in [B,T,C] layout ----
    const float inv0 = 1.0f / l0, inv1 = 1.0f / l1;
    const int bb = bh >> 4, h = bh & 15;
    const int t0 = qrow0 + g, t1 = t0 + 8;
    #pragma unroll
    for (int dt = 0; dt < 8; dt++) {
        const int col = h * 64 + dt * 8 + 2 * tg;
        uint32_t lo0, lo1;
        const uint32_t hi0 = pack_split(O[dt][0] * inv0, O[dt][1] * inv0, lo0);
        const uint32_t hi1 = pack_split(O[dt][2] * inv1, O[dt][3] * inv1, lo1);
        const size_t o0 = ((size_t)(bb * T_ + t0)) * C_ + col;
        const size_t o1 = ((size_t)(bb * T_ + t1)) * C_ + col;
        *(uint32_t*)(Yhi + o0) = hi0;
        *(uint32_t*)(Ylo + o0) = lo0;
        *(uint32_t*)(Yhi + o1) = hi1;
        *(uint32_t*)(Ylo + o1) = lo1;
    }
}

// ---------------------------------------------------------------------------
extern "C" void kernel_launch(void* const* d_in, const int* in_sizes, int n_in,
                              void* d_out, int out_size)
{
    const float* query = (const float*)d_in[0];
    const float* key   = (const float*)d_in[1];
    const float* value = (const float*)d_in[2];
    // d_in[3] = att_mask (causal tril; provably unused)
    const float* Wq = (const float*)d_in[4];
    const float* bq = (const float*)d_in[5];
    const float* Wk = (const float*)d_in[6];
    const float* bk = (const float*)d_in[7];
    const float* Wv = (const float*)d_in[8];
    const float* bv = (const float*)d_in[9];
    const float* Wp = (const float*)d_in[10];
    const float* bp = (const float*)d_in[11];
    float* out = (float*)d_out;

    __nv_bfloat16 *inhi, *inlo, *whi, *wlo;
    __nv_bfloat16 *qhi, *qlo, *khi, *klo, *vhi, *vlo, *vthi, *vtlo, *yhi, *ylo;
    cudaGetSymbolAddress((void**)&inhi, g_inhi);
    cudaGetSymbolAddress((void**)&inlo, g_inlo);
    cudaGetSymbolAddress((void**)&whi, g_whi);
    cudaGetSymbolAddress((void**)&wlo, g_wlo);
    cudaGetSymbolAddress((void**)&qhi, g_qhi);
    cudaGetSymbolAddress((void**)&qlo, g_qlo);
    cudaGetSymbolAddress((void**)&khi, g_khi);
    cudaGetSymbolAddress((void**)&klo, g_klo);
    cudaGetSymbolAddress((void**)&vhi, g_vhi);
    cudaGetSymbolAddress((void**)&vlo, g_vlo);
    cudaGetSymbolAddress((void**)&vthi, g_vthi);
    cudaGetSymbolAddress((void**)&vtlo, g_vtlo);
    cudaGetSymbolAddress((void**)&yhi, g_yhi);
    cudaGetSymbolAddress((void**)&ylo, g_ylo);

    cudaFuncSetAttribute(gemm_qkv,
                         cudaFuncAttributeMaxDynamicSharedMemorySize, GEMM_SMEM);
    cudaFuncSetAttribute(gemm_out,
                         cudaFuncAttributeMaxDynamicSharedMemorySize, GEMM_SMEM);
    cudaFuncSetAttribute(attn_mma,
                         cudaFuncAttributeMaxDynamicSharedMemorySize, ATTN_SMEM);

    // 1. split inputs (one launch)
    split3_kernel<<<dim3((M_ * C_) / 1024, 3), 256>>>(query, key, value, inhi, inlo);
    // 2. split+transpose weights (one launch)
    wsplit4_kernel<<<dim3(C_ / 32, C_ / 32, 4), dim3(32, 8)>>>(Wq, Wk, Wv, Wp, whi, wlo);
    // 3. fused QKV projection
    gemm_qkv<<<dim3(C_ / 128, M_ / 128, 3), 256, GEMM_SMEM>>>(
        inhi, inlo, whi, wlo, bq, bk, bv,
        qhi, qlo, khi, klo, vhi, vlo);
    // 4. V transpose (bf16, exact)
    vtrans_kernel<<<dim3(T_ / 32, HD_ / 32, BH_), dim3(32, 8)>>>(vhi, vlo, vthi, vtlo);
    // 5. flash attention
    attn_mma<<<dim3(T_ / 128, BH_), 256, ATTN_SMEM>>>(qhi, qlo, khi, klo,
                                                      vthi, vtlo, yhi, ylo);
    // 6. output projection
    gemm_out<<<dim3(C_ / 128, M_ / 128), 256, GEMM_SMEM>>>(
        yhi, ylo, whi + (size_t)3 * C_ * C_, wlo + (size_t)3 * C_ * C_, bp, out);
}

// round 7
// speedup vs baseline: 3.0843x; 1.0171x over previous
#include <cuda_runtime.h>
#include <cuda_bf16.h>
#include <cstdint>

// Problem constants
#define B_   2
#define T_   2048
#define C_   1024
#define H_   16
#define HD_  64
#define M_   (B_*T_)    // 4096
#define BH_  (B_*H_)    // 32
#define SM_SCALE 0.125f // 1/sqrt(64)

// ---------------------------------------------------------------------------
// Scratch (device globals: allocation-guard safe)
// ---------------------------------------------------------------------------
__device__ __nv_bfloat16 g_inhi[(size_t)3*M_*C_];   // split inputs q,k,v
__device__ __nv_bfloat16 g_inlo[(size_t)3*M_*C_];
__device__ __nv_bfloat16 g_whi[(size_t)4*C_*C_];    // W^T [4][N][K]
__device__ __nv_bfloat16 g_wlo[(size_t)4*C_*C_];
__device__ __nv_bfloat16 g_qhi[(size_t)BH_*T_*HD_];
__device__ __nv_bfloat16 g_qlo[(size_t)BH_*T_*HD_];
__device__ __nv_bfloat16 g_khi[(size_t)BH_*T_*HD_];
__device__ __nv_bfloat16 g_klo[(size_t)BH_*T_*HD_];
__device__ __nv_bfloat16 g_vhi[(size_t)BH_*T_*HD_];
__device__ __nv_bfloat16 g_vlo[(size_t)BH_*T_*HD_];
__device__ __nv_bfloat16 g_yhi[(size_t)M_*C_];
__device__ __nv_bfloat16 g_ylo[(size_t)M_*C_];

// ---------------------------------------------------------------------------
// Base-target PTX helpers
// ---------------------------------------------------------------------------
__device__ __forceinline__ uint32_t smem_u32(const void* p) {
    uint32_t a;
    asm("{ .reg .u64 t; cvta.to.shared.u64 t, %1; cvt.u32.u64 %0, t; }"
        : "=r"(a) : "l"(p));
    return a;
}
__device__ __forceinline__ void cp16(uint32_t dst, const void* src) {
    asm volatile("{ .reg .u64 g; cvta.to.global.u64 g, %1;"
                 "  cp.async.cg.shared.global [%0], [g], 16; }"
                 :: "r"(dst), "l"(src) : "memory");
}
#define CP_COMMIT() asm volatile("cp.async.commit_group;" ::: "memory")
#define CP_WAIT(N)  asm volatile("cp.async.wait_group %0;" :: "n"(N) : "memory")

__device__ __forceinline__ void ldsm_x4(uint32_t* r, uint32_t addr) {
    asm volatile("ldmatrix.sync.aligned.m8n8.x4.shared.b16 {%0,%1,%2,%3}, [%4];"
                 : "=r"(r[0]), "=r"(r[1]), "=r"(r[2]), "=r"(r[3]) : "r"(addr));
}
__device__ __forceinline__ void ldsm_x4_t(uint32_t* r, uint32_t addr) {
    asm volatile("ldmatrix.sync.aligned.m8n8.x4.trans.shared.b16 {%0,%1,%2,%3}, [%4];"
                 : "=r"(r[0]), "=r"(r[1]), "=r"(r[2]), "=r"(r[3]) : "r"(addr));
}
__device__ __forceinline__ void mma_bf16(float* c, const uint32_t* a, const uint32_t* b) {
    asm volatile(
        "mma.sync.aligned.m16n8k16.row.col.f32.bf16.bf16.f32 "
        "{%0,%1,%2,%3}, {%4,%5,%6,%7}, {%8,%9}, {%0,%1,%2,%3};"
        : "+f"(c[0]), "+f"(c[1]), "+f"(c[2]), "+f"(c[3])
        : "r"(a[0]), "r"(a[1]), "r"(a[2]), "r"(a[3]), "r"(b[0]), "r"(b[1]));
}

__device__ __forceinline__ void split1(float v, __nv_bfloat16& h, __nv_bfloat16& l) {
    h = __float2bfloat16(v);
    l = __float2bfloat16(v - __bfloat162float(h));
}
__device__ __forceinline__ uint32_t pack_split(float a, float b, uint32_t& lo) {
    __nv_bfloat16 ha = __float2bfloat16(a), hb = __float2bfloat16(b);
    float ra = a - __bfloat162float(ha);
    float rb = b - __bfloat162float(hb);
    __nv_bfloat162 Hh = __halves2bfloat162(ha, hb);
    __nv_bfloat162 Ll = __halves2bfloat162(__float2bfloat16(ra), __float2bfloat16(rb));
    lo = *(uint32_t*)&Ll;
    return *(uint32_t*)&Hh;
}

// ---------------------------------------------------------------------------
// Conversion kernels
// ---------------------------------------------------------------------------
__global__ void split3_kernel(const float* __restrict__ Q, const float* __restrict__ K,
                              const float* __restrict__ V,
                              __nv_bfloat16* __restrict__ Hi,
                              __nv_bfloat16* __restrict__ Lo)
{
    const int z = blockIdx.y;
    const float* X = (z == 0) ? Q : (z == 1) ? K : V;
    const size_t off = (size_t)z * M_ * C_;
    const int i = (blockIdx.x * blockDim.x + threadIdx.x) * 4;
    float4 v = *(const float4*)(X + i);
    __nv_bfloat16 h[4], l[4];
    split1(v.x, h[0], l[0]); split1(v.y, h[1], l[1]);
    split1(v.z, h[2], l[2]); split1(v.w, h[3], l[3]);
    *(uint2*)(Hi + off + i) = *(uint2*)h;
    *(uint2*)(Lo + off + i) = *(uint2*)l;
}

// 4 weights [K][N] fp32 -> W^T [z][N][K] bf16 hi/lo
__global__ void wsplit4_kernel(const float* __restrict__ W0, const float* __restrict__ W1,
                               const float* __restrict__ W2, const float* __restrict__ W3,
                               __nv_bfloat16* __restrict__ Hi,
                               __nv_bfloat16* __restrict__ Lo)
{
    __shared__ float tile[32][33];
    const int z = blockIdx.z;
    const float* W = (z == 0) ? W0 : (z == 1) ? W1 : (z == 2) ? W2 : W3;
    const size_t off = (size_t)z * C_ * C_;
    const int n0 = blockIdx.x * 32, k0 = blockIdx.y * 32;
    const int tx = threadIdx.x, ty = threadIdx.y;   // 32 x 8
    #pragma unroll
    for (int r = 0; r < 32; r += 8)
        tile[ty + r][tx] = W[(size_t)(k0 + ty + r) * C_ + n0 + tx];
    __syncthreads();
    #pragma unroll
    for (int r = 0; r < 32; r += 8) {
        const int n = n0 + ty + r, k = k0 + tx;
        __nv_bfloat16 h, l;
        split1(tile[tx][ty + r], h, l);
        Hi[off + (size_t)n * C_ + k] = h;
        Lo[off + (size_t)n * C_ + k] = l;
    }
}

// ---------------------------------------------------------------------------
// Shared GEMM mainloop: 128x128 tile, BK=32, double-buffered cp.async
// ---------------------------------------------------------------------------
#define PA 40
#define HALF_OFF   10240u
#define BBASE_OFF  20480u
#define BUF_BYTES  40960u
#define GEMM_SMEM  (2 * BUF_BYTES)

static __device__ __forceinline__ void gemm_mainloop(
    const __nv_bfloat16* __restrict__ Ahi, const __nv_bfloat16* __restrict__ Alo,
    const __nv_bfloat16* __restrict__ Bhi, const __nv_bfloat16* __restrict__ Blo,
    uint32_t sbase, int brow, int bcol, int tid, float acc[4][4][4])
{
    const int lane = tid & 31;
    const int wid  = tid >> 5;
    const int wm   = wid >> 2;
    const int wn   = wid & 3;
    const int r0 = tid >> 2, s0 = tid & 3;
    const int r1 = (tid + 256) >> 2;

    auto load_chunk = [&](int kc, int buf) {
        const uint32_t d0 = sbase + buf * BUF_BYTES;
        const size_t ka = (size_t)kc * 32;
        uint32_t dA0 = d0 + r0 * 80 + s0 * 16;
        uint32_t dA1 = d0 + r1 * 80 + s0 * 16;
        cp16(dA0,              Ahi + (size_t)(brow + r0) * C_ + ka + s0 * 8);
        cp16(dA1,              Ahi + (size_t)(brow + r1) * C_ + ka + s0 * 8);
        cp16(dA0 + HALF_OFF,   Alo + (size_t)(brow + r0) * C_ + ka + s0 * 8);
        cp16(dA1 + HALF_OFF,   Alo + (size_t)(brow + r1) * C_ + ka + s0 * 8);
        cp16(dA0 + BBASE_OFF,            Bhi + (size_t)(bcol + r0) * C_ + ka + s0 * 8);
        cp16(dA1 + BBASE_OFF,            Bhi + (size_t)(bcol + r1) * C_ + ka + s0 * 8);
        cp16(dA0 + BBASE_OFF + HALF_OFF, Blo + (size_t)(bcol + r0) * C_ + ka + s0 * 8);
        cp16(dA1 + BBASE_OFF + HALF_OFF, Blo + (size_t)(bcol + r1) * C_ + ka + s0 * 8);
        CP_COMMIT();
    };

    load_chunk(0, 0);

    for (int kc = 0; kc < 32; kc++) {
        const int cur = kc & 1;
        if (kc + 1 < 32) { load_chunk(kc + 1, cur ^ 1); CP_WAIT(1); }
        else             { CP_WAIT(0); }
        __syncthreads();

        const uint32_t aB = sbase + cur * BUF_BYTES;
        const uint32_t bB = aB + BBASE_OFF;

        #pragma unroll
        for (int s = 0; s < 2; s++) {
            uint32_t bh[8], bl[8];
            #pragma unroll
            for (int p = 0; p < 2; p++) {
                const int nrow = wn * 32 + p * 16 + ((lane >> 4) & 1) * 8 + (lane & 7);
                const int col  = s * 16 + ((lane >> 3) & 1) * 8;
                const uint32_t bd = bB + (nrow * PA + col) * 2;
                ldsm_x4(&bh[p * 4], bd);
                ldsm_x4(&bl[p * 4], bd + HALF_OFF);
            }
            #pragma unroll
            for (int mt = 0; mt < 4; mt++) {
                const int arow = wm * 64 + mt * 16 + (lane & 15);
                const int acol = s * 16 + ((lane >> 4) << 3);
                const uint32_t ad = aB + (arow * PA + acol) * 2;
                uint32_t af[4];
                ldsm_x4(af, ad);
                #pragma unroll
                for (int nt = 0; nt < 4; nt++) {
                    mma_bf16(acc[mt][nt], af, &bh[nt * 2]);
                    mma_bf16(acc[mt][nt], af, &bl[nt * 2]);
                }
                ldsm_x4(af, ad + HALF_OFF);
                #pragma unroll
                for (int nt = 0; nt < 4; nt++)
                    mma_bf16(acc[mt][nt], af, &bh[nt * 2]);
            }
        }
        __syncthreads();
    }
}

// ---------------------------------------------------------------------------
// Fused QKV projection GEMM: grid (8, 32, 3). Outputs bf16 hi/lo head-split.
// ---------------------------------------------------------------------------
__global__ __launch_bounds__(256, 2)
void gemm_qkv(const __nv_bfloat16* __restrict__ Inhi, const __nv_bfloat16* __restrict__ Inlo,
              const __nv_bfloat16* __restrict__ Whi, const __nv_bfloat16* __restrict__ Wlo,
              const float* __restrict__ bq, const float* __restrict__ bk,
              const float* __restrict__ bv,
              __nv_bfloat16* __restrict__ Qhi, __nv_bfloat16* __restrict__ Qlo,
              __nv_bfloat16* __restrict__ Khi, __nv_bfloat16* __restrict__ Klo,
              __nv_bfloat16* __restrict__ Vhi, __nv_bfloat16* __restrict__ Vlo)
{
    extern __shared__ char sm[];
    const uint32_t sbase = smem_u32(sm);
    const int tid  = threadIdx.x;
    const int z    = blockIdx.z;
    const int brow = blockIdx.y * 128;
    const int bcol = blockIdx.x * 128;

    const __nv_bfloat16* Ahi = Inhi + (size_t)z * M_ * C_;
    const __nv_bfloat16* Alo = Inlo + (size_t)z * M_ * C_;
    const __nv_bfloat16* Bh  = Whi + (size_t)z * C_ * C_;
    const __nv_bfloat16* Bl  = Wlo + (size_t)z * C_ * C_;
    const float* bias = (z == 0) ? bq : (z == 1) ? bk : bv;
    __nv_bfloat16* Dhi = (z == 0) ? Qhi : (z == 1) ? Khi : Vhi;
    __nv_bfloat16* Dlo = (z == 0) ? Qlo : (z == 1) ? Klo : Vlo;
    const float scale = (z == 0) ? SM_SCALE : 1.0f;

    float acc[4][4][4];
    #pragma unroll
    for (int mt = 0; mt < 4; mt++)
        #pragma unroll
        for (int nt = 0; nt < 4; nt++)
            #pragma unroll
            for (int e = 0; e < 4; e++) acc[mt][nt][e] = 0.f;

    gemm_mainloop(Ahi, Alo, Bh, Bl, sbase, brow, bcol, tid, acc);

    const int lane = tid & 31;
    const int wid  = tid >> 5;
    const int wm   = wid >> 2, wn = wid & 3;
    const int g  = lane >> 2;
    const int tg = lane & 3;
    #pragma unroll
    for (int nt = 0; nt < 4; nt++) {
        const int n = bcol + wn * 32 + nt * 8 + tg * 2;
        const float bx = bias[n], by = bias[n + 1];
        const int h = n >> 6, hd = n & 63;
        #pragma unroll
        for (int mt = 0; mt < 4; mt++) {
            const int mr0 = brow + wm * 64 + mt * 16 + g;
            const int mr1 = mr0 + 8;
            const int bb0 = mr0 >> 11, t0 = mr0 & 2047;
            const int bb1 = mr1 >> 11, t1 = mr1 & 2047;
            uint32_t lo0, lo1;
            const uint32_t hi0 = pack_split((acc[mt][nt][0] + bx) * scale,
                                            (acc[mt][nt][1] + by) * scale, lo0);
            const uint32_t hi1 = pack_split((acc[mt][nt][2] + bx) * scale,
                                            (acc[mt][nt][3] + by) * scale, lo1);
            const size_t o0 = (((size_t)(bb0 * H_ + h) * T_) + t0) * HD_ + hd;
            const size_t o1 = (((size_t)(bb1 * H_ + h) * T_) + t1) * HD_ + hd;
            *(uint32_t*)(Dhi + o0) = hi0;
            *(uint32_t*)(Dlo + o0) = lo0;
            *(uint32_t*)(Dhi + o1) = hi1;
            *(uint32_t*)(Dlo + o1) = lo1;
        }
    }
}

// ---------------------------------------------------------------------------
// Output projection GEMM
// ---------------------------------------------------------------------------
__global__ __launch_bounds__(256, 2)
void gemm_out(const __nv_bfloat16* __restrict__ Yhi, const __nv_bfloat16* __restrict__ Ylo,
              const __nv_bfloat16* __restrict__ Whi, const __nv_bfloat16* __restrict__ Wlo,
              const float* __restrict__ bias, float* __restrict__ Out)
{
    extern __shared__ char sm[];
    const uint32_t sbase = smem_u32(sm);
    const int tid  = threadIdx.x;
    const int brow = blockIdx.y * 128;
    const int bcol = blockIdx.x * 128;

    float acc[4][4][4];
    #pragma unroll
    for (int mt = 0; mt < 4; mt++)
        #pragma unroll
        for (int nt = 0; nt < 4; nt++)
            #pragma unroll
            for (int e = 0; e < 4; e++) acc[mt][nt][e] = 0.f;

    gemm_mainloop(Yhi, Ylo, Whi, Wlo, sbase, brow, bcol, tid, acc);

    const int lane = tid & 31;
    const int wid  = tid >> 5;
    const int wm   = wid >> 2, wn = wid & 3;
    const int g  = lane >> 2;
    const int tg = lane & 3;
    #pragma unroll
    for (int nt = 0; nt < 4; nt++) {
        const int n = bcol + wn * 32 + nt * 8 + tg * 2;
        const float bx = bias[n], by = bias[n + 1];
        #pragma unroll
        for (int mt = 0; mt < 4; mt++) {
            const int mr0 = brow + wm * 64 + mt * 16 + g;
            const int mr1 = mr0 + 8;
            *(float2*)(Out + (size_t)mr0 * C_ + n) =
                make_float2(acc[mt][nt][0] + bx, acc[mt][nt][1] + by);
            *(float2*)(Out + (size_t)mr1 * C_ + n) =
                make_float2(acc[mt][nt][2] + bx, acc[mt][nt][3] + by);
        }
    }
}

// ---------------------------------------------------------------------------
// Flash attention via bf16-split mma.sync.
// V consumed directly in [t][d] layout via ldmatrix.trans (no pre-transpose).
// Transient K/V fragments (low register pressure).
// ---------------------------------------------------------------------------
#define AQHI   0u
#define AQLO   18432u            // 128*144
#define ASTG0  36864u
#define ASTG_SZ 36864u           // 4 arrays * 64*144
#define AK_HI  0u
#define AV_HI  18432u
#define ATTN_SMEM (ASTG0 + 2 * ASTG_SZ)   // 110592

__global__ __launch_bounds__(256, 1)
void attn_mma(const __nv_bfloat16* __restrict__ Qhi, const __nv_bfloat16* __restrict__ Qlo,
              const __nv_bfloat16* __restrict__ Khi, const __nv_bfloat16* __restrict__ Klo,
              const __nv_bfloat16* __restrict__ Vhi, const __nv_bfloat16* __restrict__ Vlo,
              __nv_bfloat16* __restrict__ Yhi, __nv_bfloat16* __restrict__ Ylo)
{
    extern __shared__ char sm[];
    const uint32_t sbase = smem_u32(sm);
    const int tid  = threadIdx.x;
    const int lane = tid & 31;
    const int w    = tid >> 5;
    const int g    = lane >> 2;
    const int tg   = lane & 3;

    const int qt = (int)gridDim.x - 1 - (int)blockIdx.x;   // largest first
    const int bh = blockIdx.y;
    const int qrow0 = qt * 128 + w * 16;
    const int nkt = 2 * qt + 2;

    const __nv_bfloat16* qhb = Qhi + ((size_t)bh * T_ + qt * 128) * HD_;
    const __nv_bfloat16* qlb = Qlo + ((size_t)bh * T_ + qt * 128) * HD_;
    const __nv_bfloat16* khb = Khi + (size_t)bh * T_ * HD_;
    const __nv_bfloat16* klb = Klo + (size_t)bh * T_ * HD_;
    const __nv_bfloat16* vhb = Vhi + (size_t)bh * T_ * HD_;
    const __nv_bfloat16* vlb = Vlo + (size_t)bh * T_ * HD_;

    // --- Q stage (once) ---
    #pragma unroll
    for (int i = 0; i < 8; i++) {
        const int idx = tid + i * 256;
        const int arr = idx >> 10;
        const int row = (idx >> 3) & 127;
        const int seg = idx & 7;
        const __nv_bfloat16* src = (arr ? qlb : qhb) + (size_t)row * HD_ + seg * 8;
        cp16(sbase + arr * 18432u + row * 144 + seg * 16, src);
    }
    CP_COMMIT();

    auto loadKV = [&](int kt) {
        const uint32_t d0 = sbase + ASTG0 + (uint32_t)(kt & 1) * ASTG_SZ;
        #pragma unroll
        for (int i = 0; i < 8; i++) {
            const int idx = tid + i * 256;
            const int arr = idx >> 9;           // 0:Khi 1:Klo 2:Vhi 3:Vlo
            const int row = (idx >> 3) & 63;
            const int seg = idx & 7;
            const __nv_bfloat16* src;
            if (arr == 0)      src = khb + (size_t)(kt * 64 + row) * HD_ + seg * 8;
            else if (arr == 1) src = klb + (size_t)(kt * 64 + row) * HD_ + seg * 8;
            else if (arr == 2) src = vhb + (size_t)(kt * 64 + row) * HD_ + seg * 8;
            else               src = vlb + (size_t)(kt * 64 + row) * HD_ + seg * 8;
            cp16(d0 + arr * 9216u + row * 144 + seg * 16, src);
        }
        CP_COMMIT();
    };

    loadKV(0);
    CP_WAIT(0);
    __syncthreads();

    uint32_t qh[16], ql[16];
    #pragma unroll
    for (int s = 0; s < 4; s++) {
        const int arow = w * 16 + (lane & 15);
        const int acol = s * 16 + ((lane >> 4) << 3);
        const uint32_t qa = sbase + AQHI + arow * 144 + acol * 2;
        ldsm_x4(&qh[s * 4], qa);
        ldsm_x4(&ql[s * 4], qa + 18432u);
    }

    float m0 = -1e30f, m1 = -1e30f, l0 = 0.f, l1 = 0.f;
    float O[8][4];
    #pragma unroll
    for (int dt = 0; dt < 8; dt++)
        #pragma unroll
        for (int e = 0; e < 4; e++) O[dt][e] = 0.f;

    for (int kt = 0; kt < nkt; kt++) {
        if (kt + 1 < nkt) { loadKV(kt + 1); CP_WAIT(1); }
        else              { CP_WAIT(0); }
        __syncthreads();

        const uint32_t kb = sbase + ASTG0 + (uint32_t)(kt & 1) * ASTG_SZ;
        const bool active = (kt * 64 <= qrow0 + 15);
        if (active) {
            // ---- S = Q K^T (transient K frags) ----
            float S[8][4];
            #pragma unroll
            for (int nt = 0; nt < 8; nt++)
                #pragma unroll
                for (int e = 0; e < 4; e++) S[nt][e] = 0.f;

            #pragma unroll
            for (int s = 0; s < 4; s++) {
                #pragma unroll
                for (int p = 0; p < 4; p++) {
                    const int nrow = p * 16 + ((lane >> 4) & 1) * 8 + (lane & 7);
                    const int col  = s * 16 + ((lane >> 3) & 1) * 8;
                    const uint32_t ad = kb + AK_HI + nrow * 144 + col * 2;
                    uint32_t kh4[4], kl4[4];
                    ldsm_x4(kh4, ad);
                    ldsm_x4(kl4, ad + 9216u);
                    mma_bf16(S[2*p],   &qh[s*4], &kh4[0]);
                    mma_bf16(S[2*p],   &qh[s*4], &kl4[0]);
                    mma_bf16(S[2*p],   &ql[s*4], &kh4[0]);
                    mma_bf16(S[2*p+1], &qh[s*4], &kh4[2]);
                    mma_bf16(S[2*p+1], &qh[s*4], &kl4[2]);
                    mma_bf16(S[2*p+1], &ql[s*4], &kh4[2]);
                }
            }

            // ---- causal mask ----
            if (kt * 64 + 63 > qrow0) {
                const int r0 = qrow0 + g, r1 = r0 + 8;
                const int cbase = kt * 64 + 2 * tg;
                #pragma unroll
                for (int nt = 0; nt < 8; nt++) {
                    const int c0 = cbase + nt * 8;
                    if (c0     > r0) S[nt][0] = -1e30f;
                    if (c0 + 1 > r0) S[nt][1] = -1e30f;
                    if (c0     > r1) S[nt][2] = -1e30f;
                    if (c0 + 1 > r1) S[nt][3] = -1e30f;
                }
            }

            // ---- online softmax ----
            float mx0 = -1e30f, mx1 = -1e30f;
            #pragma unroll
            for (int nt = 0; nt < 8; nt++) {
                mx0 = fmaxf(mx0, fmaxf(S[nt][0], S[nt][1]));
                mx1 = fmaxf(mx1, fmaxf(S[nt][2], S[nt][3]));
            }
            mx0 = fmaxf(mx0, __shfl_xor_sync(0xffffffffu, mx0, 1));
            mx0 = fmaxf(mx0, __shfl_xor_sync(0xffffffffu, mx0, 2));
            mx1 = fmaxf(mx1, __shfl_xor_sync(0xffffffffu, mx1, 1));
            mx1 = fmaxf(mx1, __shfl_xor_sync(0xffffffffu, mx1, 2));
            const float nm0 = fmaxf(m0, mx0), nm1 = fmaxf(m1, mx1);
            const float corr0 = __expf(m0 - nm0), corr1 = __expf(m1 - nm1);
            m0 = nm0; m1 = nm1;

            float s0 = 0.f, s1 = 0.f;
            uint32_t phi[16], plo[16];
            #pragma unroll
            for (int nt = 0; nt < 8; nt++) {
                const float p0 = __expf(S[nt][0] - m0);
                const float p1 = __expf(S[nt][1] - m0);
                const float p2 = __expf(S[nt][2] - m1);
                const float p3 = __expf(S[nt][3] - m1);
                s0 += p0 + p1; s1 += p2 + p3;
                const int bi = (nt >> 1) * 4 + (nt & 1) * 2;
                phi[bi]     = pack_split(p0, p1, plo[bi]);
                phi[bi + 1] = pack_split(p2, p3, plo[bi + 1]);
            }
            s0 += __shfl_xor_sync(0xffffffffu, s0, 1);
            s0 += __shfl_xor_sync(0xffffffffu, s0, 2);
            s1 += __shfl_xor_sync(0xffffffffu, s1, 1);
            s1 += __shfl_xor_sync(0xffffffffu, s1, 2);
            l0 = l0 * corr0 + s0;
            l1 = l1 * corr1 + s1;

            #pragma unroll
            for (int dt = 0; dt < 8; dt++) {
                O[dt][0] *= corr0; O[dt][1] *= corr0;
                O[dt][2] *= corr1; O[dt][3] *= corr1;
            }

            // ---- O += P V (V in [t][d], trans ldmatrix; transient frags) ----
            #pragma unroll
            for (int p = 0; p < 4; p++) {
                #pragma unroll
                for (int j = 0; j < 4; j++) {
                    const int trow = p * 16 + ((lane >> 3) & 1) * 8 + (lane & 7);
                    const int dcol = j * 16 + ((lane >> 4) & 1) * 8;
                    const uint32_t ad = kb + AV_HI + trow * 144 + dcol * 2;
                    uint32_t vh4[4], vl4[4];
                    ldsm_x4_t(vh4, ad);
                    ldsm_x4_t(vl4, ad + 9216u);
                    mma_bf16(O[2*j],   &phi[p*4], &vh4[0]);
                    mma_bf16(O[2*j],   &phi[p*4], &vl4[0]);
                    mma_bf16(O[2*j],   &plo[p*4], &vh4[0]);
                    mma_bf16(O[2*j+1], &phi[p*4], &vh4[2]);
                    mma_bf16(O[2*j+1], &phi[p*4], &vl4[2]);
                    mma_bf16(O[2*j+1], &plo[p*4], &vh4[2]);
                }
            }
        }
        __syncthreads();
    }

    // ---- epilogue: normalize and write y hi/lo bf16 in [B,T,C] layout ----
    const float inv0 = 1.0f / l0, inv1 = 1.0f / l1;
    const int bb = bh >> 4, h = bh & 15;
    const int t0 = qrow0 + g, t1 = t0 + 8;
    #pragma unroll
    for (int dt = 0; dt < 8; dt++) {
        const int col = h * 64 + dt * 8 + 2 * tg;
        uint32_t lo0, lo1;
        const uint32_t hi0 = pack_split(O[dt][0] * inv0, O[dt][1] * inv0, lo0);
        const uint32_t hi1 = pack_split(O[dt][2] * inv1, O[dt][3] * inv1, lo1);
        const size_t o0 = ((size_t)(bb * T_ + t0)) * C_ + col;
        const size_t o1 = ((size_t)(bb * T_ + t1)) * C_ + col;
        *(uint32_t*)(Yhi + o0) = hi0;
        *(uint32_t*)(Ylo + o0) = lo0;
        *(uint32_t*)(Yhi + o1) = hi1;
        *(uint32_t*)(Ylo + o1) = lo1;
    }
}

// ---------------------------------------------------------------------------
extern "C" void kernel_launch(void* const* d_in, const int* in_sizes, int n_in,
                              void* d_out, int out_size)
{
    const float* query = (const float*)d_in[0];
    const float* key   = (const float*)d_in[1];
    const float* value = (const float*)d_in[2];
    // d_in[3] = att_mask (causal tril; provably unused)
    const float* Wq = (const float*)d_in[4];
    const float* bq = (const float*)d_in[5];
    const float* Wk = (const float*)d_in[6];
    const float* bk = (const float*)d_in[7];
    const float* Wv = (const float*)d_in[8];
    const float* bv = (const float*)d_in[9];
    const float* Wp = (const float*)d_in[10];
    const float* bp = (const float*)d_in[11];
    float* out = (float*)d_out;

    __nv_bfloat16 *inhi, *inlo, *whi, *wlo;
    __nv_bfloat16 *qhi, *qlo, *khi, *klo, *vhi, *vlo, *yhi, *ylo;
    cudaGetSymbolAddress((void**)&inhi, g_inhi);
    cudaGetSymbolAddress((void**)&inlo, g_inlo);
    cudaGetSymbolAddress((void**)&whi, g_whi);
    cudaGetSymbolAddress((void**)&wlo, g_wlo);
    cudaGetSymbolAddress((void**)&qhi, g_qhi);
    cudaGetSymbolAddress((void**)&qlo, g_qlo);
    cudaGetSymbolAddress((void**)&khi, g_khi);
    cudaGetSymbolAddress((void**)&klo, g_klo);
    cudaGetSymbolAddress((void**)&vhi, g_vhi);
    cudaGetSymbolAddress((void**)&vlo, g_vlo);
    cudaGetSymbolAddress((void**)&yhi, g_yhi);
    cudaGetSymbolAddress((void**)&ylo, g_ylo);

    cudaFuncSetAttribute(gemm_qkv,
                         cudaFuncAttributeMaxDynamicSharedMemorySize, GEMM_SMEM);
    cudaFuncSetAttribute(gemm_out,
                         cudaFuncAttributeMaxDynamicSharedMemorySize, GEMM_SMEM);
    cudaFuncSetAttribute(attn_mma,
                         cudaFuncAttributeMaxDynamicSharedMemorySize, ATTN_SMEM);

    // 1. split inputs (one launch)
    split3_kernel<<<dim3((M_ * C_) / 1024, 3), 256>>>(query, key, value, inhi, inlo);
    // 2. split+transpose weights (one launch)
    wsplit4_kernel<<<dim3(C_ / 32, C_ / 32, 4), dim3(32, 8)>>>(Wq, Wk, Wv, Wp, whi, wlo);
    // 3. fused QKV projection
    gemm_qkv<<<dim3(C_ / 128, M_ / 128, 3), 256, GEMM_SMEM>>>(
        inhi, inlo, whi, wlo, bq, bk, bv,
        qhi, qlo, khi, klo, vhi, vlo);
    // 4. flash attention (V transposed in ldmatrix unit)
    attn_mma<<<dim3(T_ / 128, BH_), 256, ATTN_SMEM>>>(qhi, qlo, khi, klo,
                                                      vhi, vlo, yhi, ylo);
    // 5. output projection
    gemm_out<<<dim3(C_ / 128, M_ / 128), 256, GEMM_SMEM>>>(
        yhi, ylo, whi + (size_t)3 * C_ * C_, wlo + (size_t)3 * C_ * C_, bp, out);
}

// round 8
// speedup vs baseline: 3.1402x; 1.0181x over previous
#include <cuda_runtime.h>
#include <cuda_bf16.h>
#include <cstdint>

// Problem constants
#define B_   2
#define T_   2048
#define C_   1024
#define H_   16
#define HD_  64
#define M_   (B_*T_)    // 4096
#define BH_  (B_*H_)    // 32
#define SM_SCALE 0.125f // 1/sqrt(64)

// ---------------------------------------------------------------------------
// Scratch (device globals: allocation-guard safe)
// ---------------------------------------------------------------------------
__device__ __nv_bfloat16 g_inhi[(size_t)3*M_*C_];   // split inputs q,k,v
__device__ __nv_bfloat16 g_inlo[(size_t)3*M_*C_];
__device__ __nv_bfloat16 g_whi[(size_t)4*C_*C_];    // W^T [4][N][K]
__device__ __nv_bfloat16 g_wlo[(size_t)4*C_*C_];
__device__ __nv_bfloat16 g_qhi[(size_t)BH_*T_*HD_];
__device__ __nv_bfloat16 g_qlo[(size_t)BH_*T_*HD_];
__device__ __nv_bfloat16 g_khi[(size_t)BH_*T_*HD_];
__device__ __nv_bfloat16 g_klo[(size_t)BH_*T_*HD_];
__device__ __nv_bfloat16 g_vhi[(size_t)BH_*T_*HD_];
__device__ __nv_bfloat16 g_vlo[(size_t)BH_*T_*HD_];
__device__ __nv_bfloat16 g_yhi[(size_t)M_*C_];
__device__ __nv_bfloat16 g_ylo[(size_t)M_*C_];

// ---------------------------------------------------------------------------
// Base-target PTX helpers
// ---------------------------------------------------------------------------
__device__ __forceinline__ uint32_t smem_u32(const void* p) {
    uint32_t a;
    asm("{ .reg .u64 t; cvta.to.shared.u64 t, %1; cvt.u32.u64 %0, t; }"
        : "=r"(a) : "l"(p));
    return a;
}
__device__ __forceinline__ void cp16(uint32_t dst, const void* src) {
    asm volatile("{ .reg .u64 g; cvta.to.global.u64 g, %1;"
                 "  cp.async.cg.shared.global [%0], [g], 16; }"
                 :: "r"(dst), "l"(src) : "memory");
}
#define CP_COMMIT() asm volatile("cp.async.commit_group;" ::: "memory")
#define CP_WAIT(N)  asm volatile("cp.async.wait_group %0;" :: "n"(N) : "memory")

__device__ __forceinline__ void ldsm_x4(uint32_t* r, uint32_t addr) {
    asm volatile("ldmatrix.sync.aligned.m8n8.x4.shared.b16 {%0,%1,%2,%3}, [%4];"
                 : "=r"(r[0]), "=r"(r[1]), "=r"(r[2]), "=r"(r[3]) : "r"(addr));
}
__device__ __forceinline__ void ldsm_x4_t(uint32_t* r, uint32_t addr) {
    asm volatile("ldmatrix.sync.aligned.m8n8.x4.trans.shared.b16 {%0,%1,%2,%3}, [%4];"
                 : "=r"(r[0]), "=r"(r[1]), "=r"(r[2]), "=r"(r[3]) : "r"(addr));
}
__device__ __forceinline__ void mma_bf16(float* c, const uint32_t* a, const uint32_t* b) {
    asm volatile(
        "mma.sync.aligned.m16n8k16.row.col.f32.bf16.bf16.f32 "
        "{%0,%1,%2,%3}, {%4,%5,%6,%7}, {%8,%9}, {%0,%1,%2,%3};"
        : "+f"(c[0]), "+f"(c[1]), "+f"(c[2]), "+f"(c[3])
        : "r"(a[0]), "r"(a[1]), "r"(a[2]), "r"(a[3]), "r"(b[0]), "r"(b[1]));
}

__device__ __forceinline__ void split1(float v, __nv_bfloat16& h, __nv_bfloat16& l) {
    h = __float2bfloat16(v);
    l = __float2bfloat16(v - __bfloat162float(h));
}
__device__ __forceinline__ uint32_t pack_split(float a, float b, uint32_t& lo) {
    __nv_bfloat16 ha = __float2bfloat16(a), hb = __float2bfloat16(b);
    float ra = a - __bfloat162float(ha);
    float rb = b - __bfloat162float(hb);
    __nv_bfloat162 Hh = __halves2bfloat162(ha, hb);
    __nv_bfloat162 Ll = __halves2bfloat162(__float2bfloat16(ra), __float2bfloat16(rb));
    lo = *(uint32_t*)&Ll;
    return *(uint32_t*)&Hh;
}

// ---------------------------------------------------------------------------
// Conversion kernels
// ---------------------------------------------------------------------------
__global__ void split3_kernel(const float* __restrict__ Q, const float* __restrict__ K,
                              const float* __restrict__ V,
                              __nv_bfloat16* __restrict__ Hi,
                              __nv_bfloat16* __restrict__ Lo)
{
    const int z = blockIdx.y;
    const float* X = (z == 0) ? Q : (z == 1) ? K : V;
    const size_t off = (size_t)z * M_ * C_;
    const int i = (blockIdx.x * blockDim.x + threadIdx.x) * 4;
    float4 v = *(const float4*)(X + i);
    __nv_bfloat16 h[4], l[4];
    split1(v.x, h[0], l[0]); split1(v.y, h[1], l[1]);
    split1(v.z, h[2], l[2]); split1(v.w, h[3], l[3]);
    *(uint2*)(Hi + off + i) = *(uint2*)h;
    *(uint2*)(Lo + off + i) = *(uint2*)l;
}

// 4 weights [K][N] fp32 -> W^T [z][N][K] bf16 hi/lo
__global__ void wsplit4_kernel(const float* __restrict__ W0, const float* __restrict__ W1,
                               const float* __restrict__ W2, const float* __restrict__ W3,
                               __nv_bfloat16* __restrict__ Hi,
                               __nv_bfloat16* __restrict__ Lo)
{
    __shared__ float tile[32][33];
    const int z = blockIdx.z;
    const float* W = (z == 0) ? W0 : (z == 1) ? W1 : (z == 2) ? W2 : W3;
    const size_t off = (size_t)z * C_ * C_;
    const int n0 = blockIdx.x * 32, k0 = blockIdx.y * 32;
    const int tx = threadIdx.x, ty = threadIdx.y;   // 32 x 8
    #pragma unroll
    for (int r = 0; r < 32; r += 8)
        tile[ty + r][tx] = W[(size_t)(k0 + ty + r) * C_ + n0 + tx];
    __syncthreads();
    #pragma unroll
    for (int r = 0; r < 32; r += 8) {
        const int n = n0 + ty + r, k = k0 + tx;
        __nv_bfloat16 h, l;
        split1(tile[tx][ty + r], h, l);
        Hi[off + (size_t)n * C_ + k] = h;
        Lo[off + (size_t)n * C_ + k] = l;
    }
}

// ---------------------------------------------------------------------------
// Shared GEMM mainloop: 128x128 tile, BK=32, double-buffered cp.async
// ---------------------------------------------------------------------------
#define PA 40
#define HALF_OFF   10240u
#define BBASE_OFF  20480u
#define BUF_BYTES  40960u
#define GEMM_SMEM  (2 * BUF_BYTES)

static __device__ __forceinline__ void gemm_mainloop(
    const __nv_bfloat16* __restrict__ Ahi, const __nv_bfloat16* __restrict__ Alo,
    const __nv_bfloat16* __restrict__ Bhi, const __nv_bfloat16* __restrict__ Blo,
    uint32_t sbase, int brow, int bcol, int tid, float acc[4][4][4])
{
    const int lane = tid & 31;
    const int wid  = tid >> 5;
    const int wm   = wid >> 2;
    const int wn   = wid & 3;
    const int r0 = tid >> 2, s0 = tid & 3;
    const int r1 = (tid + 256) >> 2;

    auto load_chunk = [&](int kc, int buf) {
        const uint32_t d0 = sbase + buf * BUF_BYTES;
        const size_t ka = (size_t)kc * 32;
        uint32_t dA0 = d0 + r0 * 80 + s0 * 16;
        uint32_t dA1 = d0 + r1 * 80 + s0 * 16;
        cp16(dA0,              Ahi + (size_t)(brow + r0) * C_ + ka + s0 * 8);
        cp16(dA1,              Ahi + (size_t)(brow + r1) * C_ + ka + s0 * 8);
        cp16(dA0 + HALF_OFF,   Alo + (size_t)(brow + r0) * C_ + ka + s0 * 8);
        cp16(dA1 + HALF_OFF,   Alo + (size_t)(brow + r1) * C_ + ka + s0 * 8);
        cp16(dA0 + BBASE_OFF,            Bhi + (size_t)(bcol + r0) * C_ + ka + s0 * 8);
        cp16(dA1 + BBASE_OFF,            Bhi + (size_t)(bcol + r1) * C_ + ka + s0 * 8);
        cp16(dA0 + BBASE_OFF + HALF_OFF, Blo + (size_t)(bcol + r0) * C_ + ka + s0 * 8);
        cp16(dA1 + BBASE_OFF + HALF_OFF, Blo + (size_t)(bcol + r1) * C_ + ka + s0 * 8);
        CP_COMMIT();
    };

    load_chunk(0, 0);

    for (int kc = 0; kc < 32; kc++) {
        const int cur = kc & 1;
        if (kc + 1 < 32) { load_chunk(kc + 1, cur ^ 1); CP_WAIT(1); }
        else             { CP_WAIT(0); }
        __syncthreads();

        const uint32_t aB = sbase + cur * BUF_BYTES;
        const uint32_t bB = aB + BBASE_OFF;

        #pragma unroll
        for (int s = 0; s < 2; s++) {
            uint32_t bh[8], bl[8];
            #pragma unroll
            for (int p = 0; p < 2; p++) {
                const int nrow = wn * 32 + p * 16 + ((lane >> 4) & 1) * 8 + (lane & 7);
                const int col  = s * 16 + ((lane >> 3) & 1) * 8;
                const uint32_t bd = bB + (nrow * PA + col) * 2;
                ldsm_x4(&bh[p * 4], bd);
                ldsm_x4(&bl[p * 4], bd + HALF_OFF);
            }
            #pragma unroll
            for (int mt = 0; mt < 4; mt++) {
                const int arow = wm * 64 + mt * 16 + (lane & 15);
                const int acol = s * 16 + ((lane >> 4) << 3);
                const uint32_t ad = aB + (arow * PA + acol) * 2;
                uint32_t af[4];
                ldsm_x4(af, ad);
                #pragma unroll
                for (int nt = 0; nt < 4; nt++) {
                    mma_bf16(acc[mt][nt], af, &bh[nt * 2]);
                    mma_bf16(acc[mt][nt], af, &bl[nt * 2]);
                }
                ldsm_x4(af, ad + HALF_OFF);
                #pragma unroll
                for (int nt = 0; nt < 4; nt++)
                    mma_bf16(acc[mt][nt], af, &bh[nt * 2]);
            }
        }
        __syncthreads();
    }
}

// ---------------------------------------------------------------------------
// Fused QKV projection GEMM: grid (8, 32, 3). Outputs bf16 hi/lo head-split.
// ---------------------------------------------------------------------------
__global__ __launch_bounds__(256, 2)
void gemm_qkv(const __nv_bfloat16* __restrict__ Inhi, const __nv_bfloat16* __restrict__ Inlo,
              const __nv_bfloat16* __restrict__ Whi, const __nv_bfloat16* __restrict__ Wlo,
              const float* __restrict__ bq, const float* __restrict__ bk,
              const float* __restrict__ bv,
              __nv_bfloat16* __restrict__ Qhi, __nv_bfloat16* __restrict__ Qlo,
              __nv_bfloat16* __restrict__ Khi, __nv_bfloat16* __restrict__ Klo,
              __nv_bfloat16* __restrict__ Vhi, __nv_bfloat16* __restrict__ Vlo)
{
    extern __shared__ char sm[];
    const uint32_t sbase = smem_u32(sm);
    const int tid  = threadIdx.x;
    const int z    = blockIdx.z;
    const int brow = blockIdx.y * 128;
    const int bcol = blockIdx.x * 128;

    const __nv_bfloat16* Ahi = Inhi + (size_t)z * M_ * C_;
    const __nv_bfloat16* Alo = Inlo + (size_t)z * M_ * C_;
    const __nv_bfloat16* Bh  = Whi + (size_t)z * C_ * C_;
    const __nv_bfloat16* Bl  = Wlo + (size_t)z * C_ * C_;
    const float* bias = (z == 0) ? bq : (z == 1) ? bk : bv;
    __nv_bfloat16* Dhi = (z == 0) ? Qhi : (z == 1) ? Khi : Vhi;
    __nv_bfloat16* Dlo = (z == 0) ? Qlo : (z == 1) ? Klo : Vlo;
    const float scale = (z == 0) ? SM_SCALE : 1.0f;

    float acc[4][4][4];
    #pragma unroll
    for (int mt = 0; mt < 4; mt++)
        #pragma unroll
        for (int nt = 0; nt < 4; nt++)
            #pragma unroll
            for (int e = 0; e < 4; e++) acc[mt][nt][e] = 0.f;

    gemm_mainloop(Ahi, Alo, Bh, Bl, sbase, brow, bcol, tid, acc);

    const int lane = tid & 31;
    const int wid  = tid >> 5;
    const int wm   = wid >> 2, wn = wid & 3;
    const int g  = lane >> 2;
    const int tg = lane & 3;
    #pragma unroll
    for (int nt = 0; nt < 4; nt++) {
        const int n = bcol + wn * 32 + nt * 8 + tg * 2;
        const float bx = bias[n], by = bias[n + 1];
        const int h = n >> 6, hd = n & 63;
        #pragma unroll
        for (int mt = 0; mt < 4; mt++) {
            const int mr0 = brow + wm * 64 + mt * 16 + g;
            const int mr1 = mr0 + 8;
            const int bb0 = mr0 >> 11, t0 = mr0 & 2047;
            const int bb1 = mr1 >> 11, t1 = mr1 & 2047;
            uint32_t lo0, lo1;
            const uint32_t hi0 = pack_split((acc[mt][nt][0] + bx) * scale,
                                            (acc[mt][nt][1] + by) * scale, lo0);
            const uint32_t hi1 = pack_split((acc[mt][nt][2] + bx) * scale,
                                            (acc[mt][nt][3] + by) * scale, lo1);
            const size_t o0 = (((size_t)(bb0 * H_ + h) * T_) + t0) * HD_ + hd;
            const size_t o1 = (((size_t)(bb1 * H_ + h) * T_) + t1) * HD_ + hd;
            *(uint32_t*)(Dhi + o0) = hi0;
            *(uint32_t*)(Dlo + o0) = lo0;
            *(uint32_t*)(Dhi + o1) = hi1;
            *(uint32_t*)(Dlo + o1) = lo1;
        }
    }
}

// ---------------------------------------------------------------------------
// Output projection GEMM
// ---------------------------------------------------------------------------
__global__ __launch_bounds__(256, 2)
void gemm_out(const __nv_bfloat16* __restrict__ Yhi, const __nv_bfloat16* __restrict__ Ylo,
              const __nv_bfloat16* __restrict__ Whi, const __nv_bfloat16* __restrict__ Wlo,
              const float* __restrict__ bias, float* __restrict__ Out)
{
    extern __shared__ char sm[];
    const uint32_t sbase = smem_u32(sm);
    const int tid  = threadIdx.x;
    const int brow = blockIdx.y * 128;
    const int bcol = blockIdx.x * 128;

    float acc[4][4][4];
    #pragma unroll
    for (int mt = 0; mt < 4; mt++)
        #pragma unroll
        for (int nt = 0; nt < 4; nt++)
            #pragma unroll
            for (int e = 0; e < 4; e++) acc[mt][nt][e] = 0.f;

    gemm_mainloop(Yhi, Ylo, Whi, Wlo, sbase, brow, bcol, tid, acc);

    const int lane = tid & 31;
    const int wid  = tid >> 5;
    const int wm   = wid >> 2, wn = wid & 3;
    const int g  = lane >> 2;
    const int tg = lane & 3;
    #pragma unroll
    for (int nt = 0; nt < 4; nt++) {
        const int n = bcol + wn * 32 + nt * 8 + tg * 2;
        const float bx = bias[n], by = bias[n + 1];
        #pragma unroll
        for (int mt = 0; mt < 4; mt++) {
            const int mr0 = brow + wm * 64 + mt * 16 + g;
            const int mr1 = mr0 + 8;
            *(float2*)(Out + (size_t)mr0 * C_ + n) =
                make_float2(acc[mt][nt][0] + bx, acc[mt][nt][1] + by);
            *(float2*)(Out + (size_t)mr1 * C_ + n) =
                make_float2(acc[mt][nt][2] + bx, acc[mt][nt][3] + by);
        }
    }
}

// ---------------------------------------------------------------------------
// Flash attention via bf16-split mma.sync.
// 128-thread CTAs (4 warps), Q tile 64 rows -> 2 CTAs/SM for cross-CTA
// latency hiding. V consumed in [t][d] layout via ldmatrix.trans.
// ---------------------------------------------------------------------------
#define AQLO_OFF 9216u            // 64*144
#define ASTG0    18432u
#define ASTG_SZ  36864u           // 4 arrays * 64*144
#define AV_OFF   18432u
#define ATTN_SMEM (ASTG0 + 2 * ASTG_SZ)   // 92160

__global__ __launch_bounds__(128, 2)
void attn_mma(const __nv_bfloat16* __restrict__ Qhi, const __nv_bfloat16* __restrict__ Qlo,
              const __nv_bfloat16* __restrict__ Khi, const __nv_bfloat16* __restrict__ Klo,
              const __nv_bfloat16* __restrict__ Vhi, const __nv_bfloat16* __restrict__ Vlo,
              __nv_bfloat16* __restrict__ Yhi, __nv_bfloat16* __restrict__ Ylo)
{
    extern __shared__ char sm[];
    const uint32_t sbase = smem_u32(sm);
    const int tid  = threadIdx.x;
    const int lane = tid & 31;
    const int w    = tid >> 5;        // 0..3
    const int g    = lane >> 2;
    const int tg   = lane & 3;

    const int qt = (int)gridDim.x - 1 - (int)blockIdx.x;   // largest first
    const int bh = blockIdx.y;
    const int qrow0 = qt * 64 + w * 16;
    const int nkt = qt + 1;

    const __nv_bfloat16* qhb = Qhi + ((size_t)bh * T_ + qt * 64) * HD_;
    const __nv_bfloat16* qlb = Qlo + ((size_t)bh * T_ + qt * 64) * HD_;
    const __nv_bfloat16* khb = Khi + (size_t)bh * T_ * HD_;
    const __nv_bfloat16* klb = Klo + (size_t)bh * T_ * HD_;
    const __nv_bfloat16* vhb = Vhi + (size_t)bh * T_ * HD_;
    const __nv_bfloat16* vlb = Vlo + (size_t)bh * T_ * HD_;

    // --- Q stage (once): 2 arrays * 64 rows * 8 segs = 1024 cp16 ---
    #pragma unroll
    for (int i = 0; i < 8; i++) {
        const int idx = tid + i * 128;
        const int arr = idx >> 9;
        const int row = (idx >> 3) & 63;
        const int seg = idx & 7;
        const __nv_bfloat16* src = (arr ? qlb : qhb) + (size_t)row * HD_ + seg * 8;
        cp16(sbase + arr * AQLO_OFF + row * 144 + seg * 16, src);
    }
    CP_COMMIT();

    auto loadKV = [&](int kt) {
        const uint32_t d0 = sbase + ASTG0 + (uint32_t)(kt & 1) * ASTG_SZ;
        #pragma unroll
        for (int i = 0; i < 16; i++) {
            const int idx = tid + i * 128;
            const int arr = idx >> 9;           // 0:Khi 1:Klo 2:Vhi 3:Vlo
            const int row = (idx >> 3) & 63;
            const int seg = idx & 7;
            const __nv_bfloat16* src;
            if (arr == 0)      src = khb + (size_t)(kt * 64 + row) * HD_ + seg * 8;
            else if (arr == 1) src = klb + (size_t)(kt * 64 + row) * HD_ + seg * 8;
            else if (arr == 2) src = vhb + (size_t)(kt * 64 + row) * HD_ + seg * 8;
            else               src = vlb + (size_t)(kt * 64 + row) * HD_ + seg * 8;
            cp16(d0 + arr * 9216u + row * 144 + seg * 16, src);
        }
        CP_COMMIT();
    };

    loadKV(0);
    CP_WAIT(0);
    __syncthreads();

    uint32_t qh[16], ql[16];
    #pragma unroll
    for (int s = 0; s < 4; s++) {
        const int arow = w * 16 + (lane & 15);
        const int acol = s * 16 + ((lane >> 4) << 3);
        const uint32_t qa = sbase + arow * 144 + acol * 2;
        ldsm_x4(&qh[s * 4], qa);
        ldsm_x4(&ql[s * 4], qa + AQLO_OFF);
    }

    float m0 = -1e30f, m1 = -1e30f, l0 = 0.f, l1 = 0.f;
    float O[8][4];
    #pragma unroll
    for (int dt = 0; dt < 8; dt++)
        #pragma unroll
        for (int e = 0; e < 4; e++) O[dt][e] = 0.f;

    for (int kt = 0; kt < nkt; kt++) {
        if (kt + 1 < nkt) { loadKV(kt + 1); CP_WAIT(1); }
        else              { CP_WAIT(0); }
        __syncthreads();

        const uint32_t kb = sbase + ASTG0 + (uint32_t)(kt & 1) * ASTG_SZ;

        // ---- S = Q K^T (transient K frags; all tiles active: kt <= qt) ----
        float S[8][4];
        #pragma unroll
        for (int nt = 0; nt < 8; nt++)
            #pragma unroll
            for (int e = 0; e < 4; e++) S[nt][e] = 0.f;

        #pragma unroll
        for (int s = 0; s < 4; s++) {
            #pragma unroll
            for (int p = 0; p < 4; p++) {
                const int nrow = p * 16 + ((lane >> 4) & 1) * 8 + (lane & 7);
                const int col  = s * 16 + ((lane >> 3) & 1) * 8;
                const uint32_t ad = kb + nrow * 144 + col * 2;
                uint32_t kh4[4], kl4[4];
                ldsm_x4(kh4, ad);
                ldsm_x4(kl4, ad + 9216u);
                mma_bf16(S[2*p],   &qh[s*4], &kh4[0]);
                mma_bf16(S[2*p],   &qh[s*4], &kl4[0]);
                mma_bf16(S[2*p],   &ql[s*4], &kh4[0]);
                mma_bf16(S[2*p+1], &qh[s*4], &kh4[2]);
                mma_bf16(S[2*p+1], &qh[s*4], &kl4[2]);
                mma_bf16(S[2*p+1], &ql[s*4], &kh4[2]);
            }
        }

        // ---- causal mask (diagonal tile only) ----
        if (kt * 64 + 63 > qrow0) {
            const int r0 = qrow0 + g, r1 = r0 + 8;
            const int cbase = kt * 64 + 2 * tg;
            #pragma unroll
            for (int nt = 0; nt < 8; nt++) {
                const int c0 = cbase + nt * 8;
                if (c0     > r0) S[nt][0] = -1e30f;
                if (c0 + 1 > r0) S[nt][1] = -1e30f;
                if (c0     > r1) S[nt][2] = -1e30f;
                if (c0 + 1 > r1) S[nt][3] = -1e30f;
            }
        }

        // ---- online softmax ----
        float mx0 = -1e30f, mx1 = -1e30f;
        #pragma unroll
        for (int nt = 0; nt < 8; nt++) {
            mx0 = fmaxf(mx0, fmaxf(S[nt][0], S[nt][1]));
            mx1 = fmaxf(mx1, fmaxf(S[nt][2], S[nt][3]));
        }
        mx0 = fmaxf(mx0, __shfl_xor_sync(0xffffffffu, mx0, 1));
        mx0 = fmaxf(mx0, __shfl_xor_sync(0xffffffffu, mx0, 2));
        mx1 = fmaxf(mx1, __shfl_xor_sync(0xffffffffu, mx1, 1));
        mx1 = fmaxf(mx1, __shfl_xor_sync(0xffffffffu, mx1, 2));
        const float nm0 = fmaxf(m0, mx0), nm1 = fmaxf(m1, mx1);
        const float corr0 = __expf(m0 - nm0), corr1 = __expf(m1 - nm1);
        m0 = nm0; m1 = nm1;

        float s0 = 0.f, s1 = 0.f;
        uint32_t phi[16], plo[16];
        #pragma unroll
        for (int nt = 0; nt < 8; nt++) {
            const float p0 = __expf(S[nt][0] - m0);
            const float p1 = __expf(S[nt][1] - m0);
            const float p2 = __expf(S[nt][2] - m1);
            const float p3 = __expf(S[nt][3] - m1);
            s0 += p0 + p1; s1 += p2 + p3;
            const int bi = (nt >> 1) * 4 + (nt & 1) * 2;
            phi[bi]     = pack_split(p0, p1, plo[bi]);
            phi[bi + 1] = pack_split(p2, p3, plo[bi + 1]);
        }
        s0 += __shfl_xor_sync(0xffffffffu, s0, 1);
        s0 += __shfl_xor_sync(0xffffffffu, s0, 2);
        s1 += __shfl_xor_sync(0xffffffffu, s1, 1);
        s1 += __shfl_xor_sync(0xffffffffu, s1, 2);
        l0 = l0 * corr0 + s0;
        l1 = l1 * corr1 + s1;

        #pragma unroll
        for (int dt = 0; dt < 8; dt++) {
            O[dt][0] *= corr0; O[dt][1] *= corr0;
            O[dt][2] *= corr1; O[dt][3] *= corr1;
        }

        // ---- O += P V (V in [t][d], trans ldmatrix; transient frags) ----
        #pragma unroll
        for (int p = 0; p < 4; p++) {
            #pragma unroll
            for (int j = 0; j < 4; j++) {
                const int trow = p * 16 + ((lane >> 3) & 1) * 8 + (lane & 7);
                const int dcol = j * 16 + ((lane >> 4) & 1) * 8;
                const uint32_t ad = kb + AV_OFF + trow * 144 + dcol * 2;
                uint32_t vh4[4], vl4[4];
                ldsm_x4_t(vh4, ad);
                ldsm_x4_t(vl4, ad + 9216u);
                mma_bf16(O[2*j],   &phi[p*4], &vh4[0]);
                mma_bf16(O[2*j],   &phi[p*4], &vl4[0]);
                mma_bf16(O[2*j],   &plo[p*4], &vh4[0]);
                mma_bf16(O[2*j+1], &phi[p*4], &vh4[2]);
                mma_bf16(O[2*j+1], &phi[p*4], &vl4[2]);
                mma_bf16(O[2*j+1], &plo[p*4], &vh4[2]);
            }
        }
        __syncthreads();
    }

    // ---- epilogue: normalize and write y hi/lo bf16 in [B,T,C] layout ----
    const float inv0 = 1.0f / l0, inv1 = 1.0f / l1;
    const int bb = bh >> 4, h = bh & 15;
    const int t0 = qrow0 + g, t1 = t0 + 8;
    #pragma unroll
    for (int dt = 0; dt < 8; dt++) {
        const int col = h * 64 + dt * 8 + 2 * tg;
        uint32_t lo0, lo1;
        const uint32_t hi0 = pack_split(O[dt][0] * inv0, O[dt][1] * inv0, lo0);
        const uint32_t hi1 = pack_split(O[dt][2] * inv1, O[dt][3] * inv1, lo1);
        const size_t o0 = ((size_t)(bb * T_ + t0)) * C_ + col;
        const size_t o1 = ((size_t)(bb * T_ + t1)) * C_ + col;
        *(uint32_t*)(Yhi + o0) = hi0;
        *(uint32_t*)(Ylo + o0) = lo0;
        *(uint32_t*)(Yhi + o1) = hi1;
        *(uint32_t*)(Ylo + o1) = lo1;
    }
}

// ---------------------------------------------------------------------------
extern "C" void kernel_launch(void* const* d_in, const int* in_sizes, int n_in,
                              void* d_out, int out_size)
{
    const float* query = (const float*)d_in[0];
    const float* key   = (const float*)d_in[1];
    const float* value = (const float*)d_in[2];
    // d_in[3] = att_mask (causal tril; provably unused)
    const float* Wq = (const float*)d_in[4];
    const float* bq = (const float*)d_in[5];
    const float* Wk = (const float*)d_in[6];
    const float* bk = (const float*)d_in[7];
    const float* Wv = (const float*)d_in[8];
    const float* bv = (const float*)d_in[9];
    const float* Wp = (const float*)d_in[10];
    const float* bp = (const float*)d_in[11];
    float* out = (float*)d_out;

    __nv_bfloat16 *inhi, *inlo, *whi, *wlo;
    __nv_bfloat16 *qhi, *qlo, *khi, *klo, *vhi, *vlo, *yhi, *ylo;
    cudaGetSymbolAddress((void**)&inhi, g_inhi);
    cudaGetSymbolAddress((void**)&inlo, g_inlo);
    cudaGetSymbolAddress((void**)&whi, g_whi);
    cudaGetSymbolAddress((void**)&wlo, g_wlo);
    cudaGetSymbolAddress((void**)&qhi, g_qhi);
    cudaGetSymbolAddress((void**)&qlo, g_qlo);
    cudaGetSymbolAddress((void**)&khi, g_khi);
    cudaGetSymbolAddress((void**)&klo, g_klo);
    cudaGetSymbolAddress((void**)&vhi, g_vhi);
    cudaGetSymbolAddress((void**)&vlo, g_vlo);
    cudaGetSymbolAddress((void**)&yhi, g_yhi);
    cudaGetSymbolAddress((void**)&ylo, g_ylo);

    cudaFuncSetAttribute(gemm_qkv,
                         cudaFuncAttributeMaxDynamicSharedMemorySize, GEMM_SMEM);
    cudaFuncSetAttribute(gemm_out,
                         cudaFuncAttributeMaxDynamicSharedMemorySize, GEMM_SMEM);
    cudaFuncSetAttribute(attn_mma,
                         cudaFuncAttributeMaxDynamicSharedMemorySize, ATTN_SMEM);

    // 1. split inputs (one launch)
    split3_kernel<<<dim3((M_ * C_) / 1024, 3), 256>>>(query, key, value, inhi, inlo);
    // 2. split+transpose weights (one launch)
    wsplit4_kernel<<<dim3(C_ / 32, C_ / 32, 4), dim3(32, 8)>>>(Wq, Wk, Wv, Wp, whi, wlo);
    // 3. fused QKV projection
    gemm_qkv<<<dim3(C_ / 128, M_ / 128, 3), 256, GEMM_SMEM>>>(
        inhi, inlo, whi, wlo, bq, bk, bv,
        qhi, qlo, khi, klo, vhi, vlo);
    // 4. flash attention (64-row Q tiles, 2 CTAs/SM)
    attn_mma<<<dim3(T_ / 64, BH_), 128, ATTN_SMEM>>>(qhi, qlo, khi, klo,
                                                     vhi, vlo, yhi, ylo);
    // 5. output projection
    gemm_out<<<dim3(C_ / 128, M_ / 128), 256, GEMM_SMEM>>>(
        yhi, ylo, whi + (size_t)3 * C_ * C_, wlo + (size_t)3 * C_ * C_, bp, out);
}